// round 10
// baseline (speedup 1.0000x reference)
#include <cuda_runtime.h>
#include <cstdint>
#include <math.h>

// Problem constants
#define DIMC    2560
#define NHEAD   40
#define HDIM    64
#define BATCH   2
#define SEQ     2048
#define MROWS   (BATCH * SEQ)                 // 4096
#define QKV_ONE ((size_t)BATCH * NHEAD * SEQ * HDIM)
#define ATTN_SCALE 0.125f

// Scratch (allocation-free rule: __device__ globals)
__device__ __align__(16) float g_qkv[3u * BATCH * NHEAD * SEQ * HDIM]; // [which][b][h][n][d]
__device__ __align__(16) float g_attn[(size_t)BATCH * SEQ * DIMC];     // [b][n][h*64+d]

// ---------------------------------------------------------------------------
// mma.sync tf32 helpers (sm_80+ PTX, compiles for plain compute_103)
// ---------------------------------------------------------------------------
__device__ __forceinline__ float f2tf32(float x) {
    uint32_t u;
    asm("cvt.rna.tf32.f32 %0, %1;" : "=r"(u) : "f"(x));
    return __uint_as_float(u);
}
__device__ __forceinline__ void mma_tf32(float* c, const uint32_t* a,
                                         uint32_t b0, uint32_t b1) {
    asm volatile(
        "mma.sync.aligned.m16n8k8.row.col.f32.tf32.tf32.f32 "
        "{%0,%1,%2,%3}, {%4,%5,%6,%7}, {%8,%9}, {%0,%1,%2,%3};"
        : "+f"(c[0]), "+f"(c[1]), "+f"(c[2]), "+f"(c[3])
        : "r"(a[0]), "r"(a[1]), "r"(a[2]), "r"(a[3]), "r"(b0), "r"(b1));
}

// ---------------------------------------------------------------------------
// TF32 tensor-core GEMM (unchanged from R7 — measured 103 TF/s)
// ---------------------------------------------------------------------------
#define SM_STRIDE   36
#define SM_TILE     (128 * SM_STRIDE)
#define SM_STAGE    (2 * SM_TILE)
#define GEMM_SMEM_BYTES (2 * SM_STAGE * 4)

template <int MODE>
__global__ __launch_bounds__(256, 2)
void mma_gemm(const float* __restrict__ Ain, const float* __restrict__ W,
              const float* __restrict__ bias, float* __restrict__ Oout, int Nout)
{
    extern __shared__ float sm[];
    const int tid  = threadIdx.x;
    const int wid  = tid >> 5;
    const int lane = tid & 31;
    const int q    = lane >> 2;
    const int lp   = lane & 3;
    const int warp_m = wid & 3;
    const int warp_n = wid >> 2;
    const int bm = blockIdx.x << 7;
    const int bn = blockIdx.y << 7;
    const int K  = DIMC;
    const int nch = K / 32;

    const float* A = (MODE == 0) ? Ain : g_attn;

    const int aM  = tid >> 3;
    const int aC4 = (tid & 7) << 2;
    const int bK  = tid & 7;
    const int bN  = (tid >> 3) << 2;

    float4 va[4], vb[4];
#pragma unroll
    for (int p = 0; p < 4; p++) {
        va[p] = *(const float4*)&A[(size_t)(bm + aM + (p << 5)) * K + aC4];
        vb[p] = *(const float4*)&W[(size_t)(bK + (p << 3)) * Nout + bn + bN];
    }

    float acc[2][8][4];
#pragma unroll
    for (int mi = 0; mi < 2; mi++)
#pragma unroll
        for (int nj = 0; nj < 8; nj++)
#pragma unroll
            for (int r = 0; r < 4; r++) acc[mi][nj][r] = 0.0f;

    {
        float* As = sm;
        float* Bs = sm + SM_TILE;
#pragma unroll
        for (int p = 0; p < 4; p++) {
            float4 t;
            t.x = f2tf32(va[p].x); t.y = f2tf32(va[p].y);
            t.z = f2tf32(va[p].z); t.w = f2tf32(va[p].w);
            *(float4*)&As[(aM + (p << 5)) * SM_STRIDE + aC4] = t;
            const int k = bK + (p << 3);
            Bs[(bN + 0) * SM_STRIDE + k] = f2tf32(vb[p].x);
            Bs[(bN + 1) * SM_STRIDE + k] = f2tf32(vb[p].y);
            Bs[(bN + 2) * SM_STRIDE + k] = f2tf32(vb[p].z);
            Bs[(bN + 3) * SM_STRIDE + k] = f2tf32(vb[p].w);
        }
    }
    __syncthreads();

    for (int c = 0; c < nch; c++) {
        const int cur = c & 1;
        const bool has_next = (c + 1 < nch);
        if (has_next) {
            const int kc = (c + 1) << 5;
#pragma unroll
            for (int p = 0; p < 4; p++) {
                va[p] = *(const float4*)&A[(size_t)(bm + aM + (p << 5)) * K + kc + aC4];
                vb[p] = *(const float4*)&W[(size_t)(kc + bK + (p << 3)) * Nout + bn + bN];
            }
        }
        {
            const float* As = sm + cur * SM_STAGE;
            const float* Bs = As + SM_TILE;
#pragma unroll
            for (int ks = 0; ks < 4; ks++) {
                const int kcol = (ks << 3) + lp;
                uint32_t a[2][4];
#pragma unroll
                for (int mi = 0; mi < 2; mi++) {
                    const int r0 = (warp_m << 5) + (mi << 4) + q;
                    a[mi][0] = __float_as_uint(As[r0 * SM_STRIDE + kcol]);
                    a[mi][1] = __float_as_uint(As[(r0 + 8) * SM_STRIDE + kcol]);
                    a[mi][2] = __float_as_uint(As[r0 * SM_STRIDE + kcol + 4]);
                    a[mi][3] = __float_as_uint(As[(r0 + 8) * SM_STRIDE + kcol + 4]);
                }
#pragma unroll
                for (int nj = 0; nj < 8; nj++) {
                    const int n = (warp_n << 6) + (nj << 3) + q;
                    const uint32_t b0 = __float_as_uint(Bs[n * SM_STRIDE + kcol]);
                    const uint32_t b1 = __float_as_uint(Bs[n * SM_STRIDE + kcol + 4]);
                    mma_tf32(acc[0][nj], a[0], b0, b1);
                    mma_tf32(acc[1][nj], a[1], b0, b1);
                }
            }
        }
        if (has_next) {
            float* As = sm + (cur ^ 1) * SM_STAGE;
            float* Bs = As + SM_TILE;
#pragma unroll
            for (int p = 0; p < 4; p++) {
                float4 t;
                t.x = f2tf32(va[p].x); t.y = f2tf32(va[p].y);
                t.z = f2tf32(va[p].z); t.w = f2tf32(va[p].w);
                *(float4*)&As[(aM + (p << 5)) * SM_STRIDE + aC4] = t;
                const int k = bK + (p << 3);
                Bs[(bN + 0) * SM_STRIDE + k] = f2tf32(vb[p].x);
                Bs[(bN + 1) * SM_STRIDE + k] = f2tf32(vb[p].y);
                Bs[(bN + 2) * SM_STRIDE + k] = f2tf32(vb[p].z);
                Bs[(bN + 3) * SM_STRIDE + k] = f2tf32(vb[p].w);
            }
        }
        __syncthreads();
    }

#pragma unroll
    for (int mi = 0; mi < 2; mi++) {
        const int row0 = bm + (warp_m << 5) + (mi << 4) + q;
#pragma unroll
        for (int nj = 0; nj < 8; nj++) {
            const int col = bn + (warp_n << 6) + (nj << 3) + (lp << 1);
            const float bx = bias[col];
            const float by = bias[col + 1];
            float2 v0 = make_float2(acc[mi][nj][0] + bx, acc[mi][nj][1] + by);
            float2 v1 = make_float2(acc[mi][nj][2] + bx, acc[mi][nj][3] + by);
            if (MODE == 0) {
                const int which = col / DIMC;
                const int cc = col - which * DIMC;
                const int hh = cc >> 6;
                const int dd = cc & 63;
                const int bb0 = row0 >> 11, nn0 = row0 & 2047;
                const int r1 = row0 + 8;
                const int bb1 = r1 >> 11, nn1 = r1 & 2047;
                const size_t base = (((size_t)which * BATCH) * NHEAD + hh) * SEQ * HDIM;
                *(float2*)&g_qkv[base + (((size_t)bb0 * NHEAD * SEQ) + nn0) * HDIM + dd] = v0;
                *(float2*)&g_qkv[base + (((size_t)bb1 * NHEAD * SEQ) + nn1) * HDIM + dd] = v1;
            } else {
                *(float2*)&Oout[(size_t)row0 * Nout + col] = v0;
                *(float2*)&Oout[(size_t)(row0 + 8) * Nout + col] = v1;
            }
        }
    }
}

// ---------------------------------------------------------------------------
// Flash attention on tf32 mma.sync.
// One CTA = (b, h, 128-query tile); 8 warps x 16 q-rows.
// Q fragments resident in registers for all 32 k-tiles.
// Smem strides chosen for conflict-free fragment LDS:
//   K/P (row index = lane>>2 pattern): stride 68 -> bank = lane
//   V   (row index = lane&3 pattern):  stride 72 -> bank = 8*(lane&3)+(lane>>2)
// ---------------------------------------------------------------------------
#define KS_STRIDE 68
#define V_STRIDE  72
#define P_STRIDE  68
#define OFF_V (64 * KS_STRIDE)
#define OFF_P (OFF_V + 64 * V_STRIDE)
#define ATTN_SMEM_BYTES ((OFF_P + 128 * P_STRIDE) * 4)   // 70656

__global__ __launch_bounds__(256, 1)
void attn_mma_kernel()
{
    extern __shared__ float sm[];
    float* Ks = sm;
    float* Vs = sm + OFF_V;
    float* Ps = sm + OFF_P;

    const int tid  = threadIdx.x;
    const int wid  = tid >> 5;
    const int lane = tid & 31;
    const int gq   = lane >> 2;     // 0..7
    const int gl   = lane & 3;      // 0..3
    const int q0   = blockIdx.x << 7;
    const int h    = blockIdx.y;
    const int b    = blockIdx.z;

    const size_t bh = ((size_t)b * NHEAD + h) * ((size_t)SEQ * HDIM);
    const float* Qg = g_qkv + bh + (size_t)q0 * HDIM;
    const float* Kg = g_qkv + QKV_ONE + bh;
    const float* Vg = g_qkv + 2 * QKV_ONE + bh;

    // ---- Stage Q (128x64) through Ps, load register fragments, pre-scaled ----
#pragma unroll
    for (int p = 0; p < 8; p++) {
        const int idx = tid + (p << 8);
        const int row = idx >> 4;
        const int c4  = (idx & 15) << 2;
        const float4 v = *(const float4*)(Qg + ((size_t)row << 6) + c4);
        float* d = &Ps[row * P_STRIDE + c4];
        d[0] = f2tf32(v.x * ATTN_SCALE);
        d[1] = f2tf32(v.y * ATTN_SCALE);
        d[2] = f2tf32(v.z * ATTN_SCALE);
        d[3] = f2tf32(v.w * ATTN_SCALE);
    }
    __syncthreads();

    const int qr = (wid << 4) + gq;      // warp-local base q row (and +8)
    uint32_t aq[8][4];
#pragma unroll
    for (int ks = 0; ks < 8; ks++) {
        const int kc = (ks << 3) + gl;
        aq[ks][0] = __float_as_uint(Ps[qr * P_STRIDE + kc]);
        aq[ks][1] = __float_as_uint(Ps[(qr + 8) * P_STRIDE + kc]);
        aq[ks][2] = __float_as_uint(Ps[qr * P_STRIDE + kc + 4]);
        aq[ks][3] = __float_as_uint(Ps[(qr + 8) * P_STRIDE + kc + 4]);
    }
    __syncthreads();   // done using Ps as Q stage

    // ---- K/V tile staging (64x64 each): 4 float4 per thread per tile ----
    const int sRow = tid >> 2;            // 0..63
    const int sC4  = (tid & 3) << 2;      // 0,4,8,12 ; +16 per p
    float4 pk[4], pv[4];
#pragma unroll
    for (int p = 0; p < 4; p++) {
        pk[p] = *(const float4*)(Kg + ((size_t)sRow << 6) + sC4 + (p << 4));
        pv[p] = *(const float4*)(Vg + ((size_t)sRow << 6) + sC4 + (p << 4));
    }
#pragma unroll
    for (int p = 0; p < 4; p++) {
        const int c = sC4 + (p << 4);
        float* dk = &Ks[sRow * KS_STRIDE + c];
        dk[0] = f2tf32(pk[p].x); dk[1] = f2tf32(pk[p].y);
        dk[2] = f2tf32(pk[p].z); dk[3] = f2tf32(pk[p].w);
        float* dv = &Vs[sRow * V_STRIDE + c];
        dv[0] = f2tf32(pv[p].x); dv[1] = f2tf32(pv[p].y);
        dv[2] = f2tf32(pv[p].z); dv[3] = f2tf32(pv[p].w);
    }
    __syncthreads();

    float Oacc[8][4];
#pragma unroll
    for (int nj = 0; nj < 8; nj++)
#pragma unroll
        for (int r = 0; r < 4; r++) Oacc[nj][r] = 0.0f;
    float m0 = -1e30f, m1 = -1e30f, l0 = 0.0f, l1 = 0.0f;

    for (int kt = 0; kt < SEQ / 64; kt++) {
        const bool has_next = (kt + 1 < SEQ / 64);
        if (has_next) {
            const float* Kt = Kg + (((size_t)(kt + 1)) << 6) * HDIM;
            const float* Vt = Vg + (((size_t)(kt + 1)) << 6) * HDIM;
#pragma unroll
            for (int p = 0; p < 4; p++) {
                pk[p] = *(const float4*)(Kt + ((size_t)sRow << 6) + sC4 + (p << 4));
                pv[p] = *(const float4*)(Vt + ((size_t)sRow << 6) + sC4 + (p << 4));
            }
        }

        // ---- S = Q K^T : 8 n-tiles x 8 k-steps ----
        float s[8][4];
#pragma unroll
        for (int nj = 0; nj < 8; nj++) {
            s[nj][0] = 0.0f; s[nj][1] = 0.0f; s[nj][2] = 0.0f; s[nj][3] = 0.0f;
            const int nrow = (nj << 3) + gq;
#pragma unroll
            for (int ks = 0; ks < 8; ks++) {
                const int kc = (ks << 3) + gl;
                const uint32_t b0 = __float_as_uint(Ks[nrow * KS_STRIDE + kc]);
                const uint32_t b1 = __float_as_uint(Ks[nrow * KS_STRIDE + kc + 4]);
                mma_tf32(s[nj], aq[ks], b0, b1);
            }
        }

        // ---- Online softmax (rows qr and qr+8, quad-reduced over lane bits 0,1) ----
        float c0 = -1e30f, c1 = -1e30f;
#pragma unroll
        for (int nj = 0; nj < 8; nj++) {
            c0 = fmaxf(c0, fmaxf(s[nj][0], s[nj][1]));
            c1 = fmaxf(c1, fmaxf(s[nj][2], s[nj][3]));
        }
        c0 = fmaxf(c0, __shfl_xor_sync(0xffffffffu, c0, 1));
        c0 = fmaxf(c0, __shfl_xor_sync(0xffffffffu, c0, 2));
        c1 = fmaxf(c1, __shfl_xor_sync(0xffffffffu, c1, 1));
        c1 = fmaxf(c1, __shfl_xor_sync(0xffffffffu, c1, 2));
        const float mn0 = fmaxf(m0, c0);
        const float mn1 = fmaxf(m1, c1);
        const float al0 = __expf(m0 - mn0);
        const float al1 = __expf(m1 - mn1);
        m0 = mn0; m1 = mn1;

        float r0 = 0.0f, r1 = 0.0f;
#pragma unroll
        for (int nj = 0; nj < 8; nj++) {
            s[nj][0] = __expf(s[nj][0] - mn0);
            s[nj][1] = __expf(s[nj][1] - mn0);
            s[nj][2] = __expf(s[nj][2] - mn1);
            s[nj][3] = __expf(s[nj][3] - mn1);
            r0 += s[nj][0] + s[nj][1];
            r1 += s[nj][2] + s[nj][3];
        }
        r0 += __shfl_xor_sync(0xffffffffu, r0, 1);
        r0 += __shfl_xor_sync(0xffffffffu, r0, 2);
        r1 += __shfl_xor_sync(0xffffffffu, r1, 1);
        r1 += __shfl_xor_sync(0xffffffffu, r1, 2);
        l0 = l0 * al0 + r0;
        l1 = l1 * al1 + r1;
#pragma unroll
        for (int nj = 0; nj < 8; nj++) {
            Oacc[nj][0] *= al0; Oacc[nj][1] *= al0;
            Oacc[nj][2] *= al1; Oacc[nj][3] *= al1;
        }

        // ---- P -> per-warp-private smem strip (rows qr, qr+8 only) ----
#pragma unroll
        for (int nj = 0; nj < 8; nj++) {
            const int col = (nj << 3) + (gl << 1);
            *(float2*)&Ps[qr * P_STRIDE + col] =
                make_float2(f2tf32(s[nj][0]), f2tf32(s[nj][1]));
            *(float2*)&Ps[(qr + 8) * P_STRIDE + col] =
                make_float2(f2tf32(s[nj][2]), f2tf32(s[nj][3]));
        }
        __syncwarp();

        // ---- O += P V : 8 k-steps (key) x 8 n-tiles (d) ----
#pragma unroll
        for (int ks = 0; ks < 8; ks++) {
            const int kc = (ks << 3) + gl;
            uint32_t pa[4];
            pa[0] = __float_as_uint(Ps[qr * P_STRIDE + kc]);
            pa[1] = __float_as_uint(Ps[(qr + 8) * P_STRIDE + kc]);
            pa[2] = __float_as_uint(Ps[qr * P_STRIDE + kc + 4]);
            pa[3] = __float_as_uint(Ps[(qr + 8) * P_STRIDE + kc + 4]);
#pragma unroll
            for (int nj = 0; nj < 8; nj++) {
                const int d = (nj << 3) + gq;
                const uint32_t b0 = __float_as_uint(Vs[((ks << 3) + gl) * V_STRIDE + d]);
                const uint32_t b1 = __float_as_uint(Vs[((ks << 3) + gl + 4) * V_STRIDE + d]);
                mma_tf32(Oacc[nj], pa, b0, b1);
            }
        }

        __syncthreads();   // all warps done with Ks/Vs
        if (has_next) {
#pragma unroll
            for (int p = 0; p < 4; p++) {
                const int c = sC4 + (p << 4);
                float* dk = &Ks[sRow * KS_STRIDE + c];
                dk[0] = f2tf32(pk[p].x); dk[1] = f2tf32(pk[p].y);
                dk[2] = f2tf32(pk[p].z); dk[3] = f2tf32(pk[p].w);
                float* dv = &Vs[sRow * V_STRIDE + c];
                dv[0] = f2tf32(pv[p].x); dv[1] = f2tf32(pv[p].y);
                dv[2] = f2tf32(pv[p].z); dv[3] = f2tf32(pv[p].w);
            }
            __syncthreads();
        }
    }

    // ---- Epilogue: normalize, write g_attn[b][n][h*64+d] ----
    const float inv0 = 1.0f / l0;
    const float inv1 = 1.0f / l1;
    const int n0 = q0 + qr;
    float* dst0 = &g_attn[((size_t)b * SEQ + n0) * DIMC + h * HDIM];
    float* dst1 = &g_attn[((size_t)b * SEQ + n0 + 8) * DIMC + h * HDIM];
#pragma unroll
    for (int nj = 0; nj < 8; nj++) {
        const int col = (nj << 3) + (gl << 1);
        *(float2*)(dst0 + col) = make_float2(Oacc[nj][0] * inv0, Oacc[nj][1] * inv0);
        *(float2*)(dst1 + col) = make_float2(Oacc[nj][2] * inv1, Oacc[nj][3] * inv1);
    }
}

// ---------------------------------------------------------------------------
extern "C" void kernel_launch(void* const* d_in, const int* in_sizes, int n_in,
                              void* d_out, int out_size)
{
    (void)in_sizes; (void)n_in; (void)out_size;
    const float* x      = (const float*)d_in[0];
    const float* w_qkv  = (const float*)d_in[1];
    const float* b_qkv  = (const float*)d_in[2];
    const float* w_proj = (const float*)d_in[3];
    const float* b_proj = (const float*)d_in[4];
    float* out = (float*)d_out;

    cudaFuncSetAttribute(mma_gemm<0>, cudaFuncAttributeMaxDynamicSharedMemorySize, GEMM_SMEM_BYTES);
    cudaFuncSetAttribute(mma_gemm<1>, cudaFuncAttributeMaxDynamicSharedMemorySize, GEMM_SMEM_BYTES);
    cudaFuncSetAttribute(attn_mma_kernel, cudaFuncAttributeMaxDynamicSharedMemorySize, ATTN_SMEM_BYTES);

    // 1) QKV GEMM (tf32 mma.sync): [4096,2560]@[2560,7680]+bias -> g_qkv
    {
        dim3 grid(MROWS / 128, 3 * DIMC / 128);
        mma_gemm<0><<<grid, 256, GEMM_SMEM_BYTES>>>(x, w_qkv, b_qkv, nullptr, 3 * DIMC);
    }
    // 2) Attention (tf32 mma.sync) -> g_attn
    {
        dim3 grid(SEQ / 128, NHEAD, BATCH);     // (16, 40, 2) = 1280 CTAs
        attn_mma_kernel<<<grid, 256, ATTN_SMEM_BYTES>>>();
    }
    // 3) Projection GEMM (tf32 mma.sync): [4096,2560]@[2560,2560]+bias -> d_out
    {
        dim3 grid(MROWS / 128, DIMC / 128);
        mma_gemm<1><<<grid, 256, GEMM_SMEM_BYTES>>>(nullptr, w_proj, b_proj, out, DIMC);
    }
}

// round 11
// speedup vs baseline: 1.4791x; 1.4791x over previous
#include <cuda_runtime.h>
#include <cstdint>
#include <math.h>

#define DIMC    2560
#define NHEAD   40
#define HDIM    64
#define BATCH   2
#define SEQ     2048
#define MROWS   (BATCH * SEQ)
#define QKV_ONE ((size_t)BATCH * NHEAD * SEQ * HDIM)
#define ATTN_SCALE 0.125f

// Scratch (__device__ globals; allocation-free rule)
__device__ __align__(16) float g_qkv[3u * BATCH * NHEAD * SEQ * HDIM]; // tf32-rounded, Q pre-scaled
__device__ __align__(16) float g_attn[(size_t)MROWS * DIMC];           // tf32-rounded
__device__ __align__(16) float g_x[(size_t)MROWS * DIMC];              // tf32-rounded x
__device__ __align__(16) float g_wqkv[(size_t)DIMC * 3 * DIMC];        // tf32-rounded w_qkv
__device__ __align__(16) float g_wproj[(size_t)DIMC * DIMC];           // tf32-rounded w_proj

// ---------------------------------------------------------------------------
__device__ __forceinline__ float f2tf32(float x) {
    uint32_t u;
    asm("cvt.rna.tf32.f32 %0, %1;" : "=r"(u) : "f"(x));
    return __uint_as_float(u);
}
__device__ __forceinline__ void mma_tf32(float* c, const uint32_t* a,
                                         uint32_t b0, uint32_t b1) {
    asm volatile(
        "mma.sync.aligned.m16n8k8.row.col.f32.tf32.tf32.f32 "
        "{%0,%1,%2,%3}, {%4,%5,%6,%7}, {%8,%9}, {%0,%1,%2,%3};"
        : "+f"(c[0]), "+f"(c[1]), "+f"(c[2]), "+f"(c[3])
        : "r"(a[0]), "r"(a[1]), "r"(a[2]), "r"(a[3]), "r"(b0), "r"(b1));
}
__device__ __forceinline__ uint32_t smem_u32(const void* p) {
    uint32_t a;
    asm("{ .reg .u64 t; cvta.to.shared.u64 t, %1; cvt.u32.u64 %0, t; }" : "=r"(a) : "l"(p));
    return a;
}
#define CP_ASYNC16(dst, src) \
    asm volatile("cp.async.cg.shared.global [%0], [%1], 16;" :: "r"(dst), "l"(src) : "memory")
#define CP_COMMIT() asm volatile("cp.async.commit_group;" ::: "memory")
#define CP_WAIT2()  asm volatile("cp.async.wait_group 2;" ::: "memory")

// ---------------------------------------------------------------------------
// Pre-pass: tf32-round inputs into scratch. which: 0=x, 1=w_qkv, 2=w_proj
// ---------------------------------------------------------------------------
__global__ void round_tf32_kernel(const float4* __restrict__ src, int which, int n4)
{
    float4* dst = (which == 0) ? (float4*)g_x
                : (which == 1) ? (float4*)g_wqkv : (float4*)g_wproj;
    const int stride = gridDim.x * blockDim.x;
    for (int i = blockIdx.x * blockDim.x + threadIdx.x; i < n4; i += stride) {
        float4 v = src[i];
        v.x = f2tf32(v.x); v.y = f2tf32(v.y);
        v.z = f2tf32(v.z); v.w = f2tf32(v.w);
        dst[i] = v;
    }
}

// ---------------------------------------------------------------------------
// TF32 GEMM: CTA 128x256, BK=32, 8 warps (warp tile 64x64), 4-stage cp.async.
// A stage layout: As[m][ (k4 ^ 4*(m&7)) + k%4 ]   (128 x 32 floats)
// B stage layout: Bs[k][ n ^ 8*(k&3) ]            (32 x 256 floats)
// Fragment LDS conflict-free (32 banks covered; derivation in commit msg).
// MODE 0: g_x @ g_wqkv + b -> g_qkv (rounded, Q pre-scaled)
// MODE 1: g_attn @ g_wproj + b -> Oout (fp32)
// ---------------------------------------------------------------------------
#define G_STAGE_FL 12288                      // 4096 A + 8192 B floats
#define GEMM_SMEM_BYTES (4 * G_STAGE_FL * 4)  // 196608

template <int MODE>
__global__ __launch_bounds__(256, 1)
void mma_gemm(const float* __restrict__ bias, float* __restrict__ Oout)
{
    extern __shared__ float sm[];
    const uint32_t smb = smem_u32(sm);
    const int tid  = threadIdx.x;
    const int wid  = tid >> 5;
    const int lane = tid & 31;
    const int q    = lane >> 2;
    const int lp   = lane & 3;
    const int wm   = wid & 1;        // 64-row strip
    const int wn   = wid >> 1;       // 64-col strip
    const int bm   = blockIdx.x << 7;
    const int bn   = blockIdx.y << 8;
    const int K    = DIMC;
    const int nch  = K / 32;         // 80
    const int Nout = (MODE == 0) ? 3 * DIMC : DIMC;

    const float* Ag = (MODE == 0) ? g_x : g_attn;
    const float* W  = (MODE == 0) ? g_wqkv : g_wproj;

    // Loader mapping
    const int lm  = tid >> 3;                      // A row (+32 per p)
    const int lc4 = (tid & 7) << 2;                // A k-chunk
    const uint32_t a_sw = (uint32_t)(lc4 ^ ((lm & 7) << 2));
    const int lk0 = tid >> 6;                      // B k (+4 per p)
    const int ln  = (tid & 63) << 2;               // B n-chunk
    const uint32_t b_sw = (uint32_t)(ln ^ (lk0 << 3));

    const float* Abase = Ag + (size_t)(bm + lm) * K + lc4;
    const float* Wbase = W + (size_t)lk0 * Nout + bn + ln;

    float acc[4][8][4];
#pragma unroll
    for (int mi = 0; mi < 4; mi++)
#pragma unroll
        for (int nj = 0; nj < 8; nj++)
#pragma unroll
            for (int r = 0; r < 4; r++) acc[mi][nj][r] = 0.0f;

#pragma unroll
    for (int s = 0; s < 3; s++) {      // prologue: stages 0..2
        const uint32_t sb = smb + (uint32_t)s * (G_STAGE_FL * 4);
        const int kc = s << 5;
#pragma unroll
        for (int p = 0; p < 4; p++)
            CP_ASYNC16(sb + ((((uint32_t)(lm + (p << 5))) << 5) + a_sw) * 4u,
                       Abase + kc + (size_t)(p << 5) * K);
#pragma unroll
        for (int p = 0; p < 8; p++)
            CP_ASYNC16(sb + 16384u + ((((uint32_t)(lk0 + (p << 2))) << 8) + b_sw) * 4u,
                       Wbase + (size_t)(kc + (p << 2)) * Nout);
        CP_COMMIT();
    }

    for (int c = 0; c < nch; c++) {
        CP_WAIT2();
        __syncthreads();
        if (c + 3 < nch) {
            const uint32_t sb = smb + (uint32_t)((c + 3) & 3) * (G_STAGE_FL * 4);
            const int kc = (c + 3) << 5;
#pragma unroll
            for (int p = 0; p < 4; p++)
                CP_ASYNC16(sb + ((((uint32_t)(lm + (p << 5))) << 5) + a_sw) * 4u,
                           Abase + kc + (size_t)(p << 5) * K);
#pragma unroll
            for (int p = 0; p < 8; p++)
                CP_ASYNC16(sb + 16384u + ((((uint32_t)(lk0 + (p << 2))) << 8) + b_sw) * 4u,
                           Wbase + (size_t)(kc + (p << 2)) * Nout);
        }
        CP_COMMIT();   // empty group at tail keeps wait_group count semantics

        const float* As = sm + (c & 3) * G_STAGE_FL;
        const float* Bs = As + 4096;
#pragma unroll
        for (int ks = 0; ks < 4; ks++) {
            const int off0 = ((ks << 3) + lp) ^ (q << 2);
            const int off4 = off0 ^ 4;
            uint32_t a[4][4];
#pragma unroll
            for (int mi = 0; mi < 4; mi++) {
                const float* ap = As + (((wm << 6) + (mi << 4) + q) << 5);
                a[mi][0] = __float_as_uint(ap[off0]);
                a[mi][1] = __float_as_uint(ap[256 + off0]);
                a[mi][2] = __float_as_uint(ap[off4]);
                a[mi][3] = __float_as_uint(ap[256 + off4]);
            }
#pragma unroll
            for (int nj = 0; nj < 8; nj++) {
                const float* bp = Bs + (((ks << 3) + lp) << 8)
                                     + (wn << 6) + ((nj ^ lp) << 3) + q;
                const uint32_t b0 = __float_as_uint(bp[0]);
                const uint32_t b1 = __float_as_uint(bp[1024]);
#pragma unroll
                for (int mi = 0; mi < 4; mi++)
                    mma_tf32(acc[mi][nj], a[mi], b0, b1);
            }
        }
    }

    // Epilogue: c0,c1 -> row r0 cols 2lp,2lp+1 ; c2,c3 -> row r0+8
#pragma unroll
    for (int mi = 0; mi < 4; mi++) {
        const int r0 = bm + (wm << 6) + (mi << 4) + q;
#pragma unroll
        for (int nj = 0; nj < 8; nj++) {
            const int col = bn + (wn << 6) + (nj << 3) + (lp << 1);
            const float bx = bias[col];
            const float by = bias[col + 1];
            if (MODE == 0) {
                const int which = col / DIMC;
                const int cc = col - which * DIMC;
                const int hh = cc >> 6;
                const int dd = cc & 63;
                const float sc = (which == 0) ? ATTN_SCALE : 1.0f;
                const int bb0 = r0 >> 11, nn0 = r0 & 2047;
                const int r1 = r0 + 8;
                const int bb1 = r1 >> 11, nn1 = r1 & 2047;
                const size_t base = (((size_t)which * BATCH) * NHEAD + hh) * SEQ * HDIM;
                float2 v0 = make_float2(f2tf32((acc[mi][nj][0] + bx) * sc),
                                        f2tf32((acc[mi][nj][1] + by) * sc));
                float2 v1 = make_float2(f2tf32((acc[mi][nj][2] + bx) * sc),
                                        f2tf32((acc[mi][nj][3] + by) * sc));
                *(float2*)&g_qkv[base + (((size_t)bb0 * NHEAD * SEQ) + nn0) * HDIM + dd] = v0;
                *(float2*)&g_qkv[base + (((size_t)bb1 * NHEAD * SEQ) + nn1) * HDIM + dd] = v1;
            } else {
                *(float2*)&Oout[(size_t)r0 * DIMC + col] =
                    make_float2(acc[mi][nj][0] + bx, acc[mi][nj][1] + by);
                *(float2*)&Oout[(size_t)(r0 + 8) * DIMC + col] =
                    make_float2(acc[mi][nj][2] + bx, acc[mi][nj][3] + by);
            }
        }
    }
}

// ---------------------------------------------------------------------------
// Flash attention, tf32 mma.sync (R8 structure; inputs pre-rounded/pre-scaled
// in g_qkv so staging is pure copy; output rounded for proj cp.async).
// ---------------------------------------------------------------------------
#define KS_STRIDE 68
#define V_STRIDE  72
#define P_STRIDE  68
#define OFF_V (64 * KS_STRIDE)
#define OFF_P (OFF_V + 64 * V_STRIDE)
#define ATTN_SMEM_BYTES ((OFF_P + 128 * P_STRIDE) * 4)

__global__ __launch_bounds__(256, 1)
void attn_mma_kernel()
{
    extern __shared__ float sm[];
    float* Ks = sm;
    float* Vs = sm + OFF_V;
    float* Ps = sm + OFF_P;

    const int tid  = threadIdx.x;
    const int wid  = tid >> 5;
    const int lane = tid & 31;
    const int gq   = lane >> 2;
    const int gl   = lane & 3;
    const int q0   = blockIdx.x << 7;
    const int h    = blockIdx.y;
    const int b    = blockIdx.z;

    const size_t bh = ((size_t)b * NHEAD + h) * ((size_t)SEQ * HDIM);
    const float* Qg = g_qkv + bh + ((size_t)q0 << 6);
    const float* Kg = g_qkv + QKV_ONE + bh;
    const float* Vg = g_qkv + 2 * QKV_ONE + bh;

    // Q stage (pre-scaled, pre-rounded): plain copy
#pragma unroll
    for (int p = 0; p < 8; p++) {
        const int idx = tid + (p << 8);
        const int row = idx >> 4;
        const int c4  = (idx & 15) << 2;
        const float4 v = *(const float4*)(Qg + ((size_t)row << 6) + c4);
        float* d = &Ps[row * P_STRIDE + c4];
        d[0] = v.x; d[1] = v.y; d[2] = v.z; d[3] = v.w;
    }
    __syncthreads();

    const int qr = (wid << 4) + gq;
    uint32_t aq[8][4];
#pragma unroll
    for (int ks = 0; ks < 8; ks++) {
        const int kc = (ks << 3) + gl;
        aq[ks][0] = __float_as_uint(Ps[qr * P_STRIDE + kc]);
        aq[ks][1] = __float_as_uint(Ps[(qr + 8) * P_STRIDE + kc]);
        aq[ks][2] = __float_as_uint(Ps[qr * P_STRIDE + kc + 4]);
        aq[ks][3] = __float_as_uint(Ps[(qr + 8) * P_STRIDE + kc + 4]);
    }
    __syncthreads();

    const int sRow = tid >> 2;
    const int sC4  = (tid & 3) << 2;
    float4 pk[4], pv[4];
#pragma unroll
    for (int p = 0; p < 4; p++) {
        pk[p] = *(const float4*)(Kg + ((size_t)sRow << 6) + sC4 + (p << 4));
        pv[p] = *(const float4*)(Vg + ((size_t)sRow << 6) + sC4 + (p << 4));
    }
#pragma unroll
    for (int p = 0; p < 4; p++) {
        const int c = sC4 + (p << 4);
        *(float4*)&Ks[sRow * KS_STRIDE + c] = pk[p];
        *(float4*)&Vs[sRow * V_STRIDE + c] = pv[p];
    }
    __syncthreads();

    float Oacc[8][4];
#pragma unroll
    for (int nj = 0; nj < 8; nj++)
#pragma unroll
        for (int r = 0; r < 4; r++) Oacc[nj][r] = 0.0f;
    float m0 = -1e30f, m1 = -1e30f, l0 = 0.0f, l1 = 0.0f;

    for (int kt = 0; kt < SEQ / 64; kt++) {
        const bool has_next = (kt + 1 < SEQ / 64);
        if (has_next) {
            const float* Kt = Kg + (((size_t)(kt + 1)) << 6) * HDIM;
            const float* Vt = Vg + (((size_t)(kt + 1)) << 6) * HDIM;
#pragma unroll
            for (int p = 0; p < 4; p++) {
                pk[p] = *(const float4*)(Kt + ((size_t)sRow << 6) + sC4 + (p << 4));
                pv[p] = *(const float4*)(Vt + ((size_t)sRow << 6) + sC4 + (p << 4));
            }
        }

        float s[8][4];
#pragma unroll
        for (int nj = 0; nj < 8; nj++) {
            s[nj][0] = 0.0f; s[nj][1] = 0.0f; s[nj][2] = 0.0f; s[nj][3] = 0.0f;
            const int nrow = (nj << 3) + gq;
#pragma unroll
            for (int ks = 0; ks < 8; ks++) {
                const int kc = (ks << 3) + gl;
                const uint32_t b0 = __float_as_uint(Ks[nrow * KS_STRIDE + kc]);
                const uint32_t b1 = __float_as_uint(Ks[nrow * KS_STRIDE + kc + 4]);
                mma_tf32(s[nj], aq[ks], b0, b1);
            }
        }

        float c0 = -1e30f, c1 = -1e30f;
#pragma unroll
        for (int nj = 0; nj < 8; nj++) {
            c0 = fmaxf(c0, fmaxf(s[nj][0], s[nj][1]));
            c1 = fmaxf(c1, fmaxf(s[nj][2], s[nj][3]));
        }
        c0 = fmaxf(c0, __shfl_xor_sync(0xffffffffu, c0, 1));
        c0 = fmaxf(c0, __shfl_xor_sync(0xffffffffu, c0, 2));
        c1 = fmaxf(c1, __shfl_xor_sync(0xffffffffu, c1, 1));
        c1 = fmaxf(c1, __shfl_xor_sync(0xffffffffu, c1, 2));
        const float mn0 = fmaxf(m0, c0);
        const float mn1 = fmaxf(m1, c1);
        const float al0 = __expf(m0 - mn0);
        const float al1 = __expf(m1 - mn1);
        m0 = mn0; m1 = mn1;

        float r0 = 0.0f, r1 = 0.0f;
#pragma unroll
        for (int nj = 0; nj < 8; nj++) {
            s[nj][0] = __expf(s[nj][0] - mn0);
            s[nj][1] = __expf(s[nj][1] - mn0);
            s[nj][2] = __expf(s[nj][2] - mn1);
            s[nj][3] = __expf(s[nj][3] - mn1);
            r0 += s[nj][0] + s[nj][1];
            r1 += s[nj][2] + s[nj][3];
        }
        r0 += __shfl_xor_sync(0xffffffffu, r0, 1);
        r0 += __shfl_xor_sync(0xffffffffu, r0, 2);
        r1 += __shfl_xor_sync(0xffffffffu, r1, 1);
        r1 += __shfl_xor_sync(0xffffffffu, r1, 2);
        l0 = l0 * al0 + r0;
        l1 = l1 * al1 + r1;
#pragma unroll
        for (int nj = 0; nj < 8; nj++) {
            Oacc[nj][0] *= al0; Oacc[nj][1] *= al0;
            Oacc[nj][2] *= al1; Oacc[nj][3] *= al1;
        }

#pragma unroll
        for (int nj = 0; nj < 8; nj++) {
            const int col = (nj << 3) + (gl << 1);
            *(float2*)&Ps[qr * P_STRIDE + col] =
                make_float2(f2tf32(s[nj][0]), f2tf32(s[nj][1]));
            *(float2*)&Ps[(qr + 8) * P_STRIDE + col] =
                make_float2(f2tf32(s[nj][2]), f2tf32(s[nj][3]));
        }
        __syncwarp();

#pragma unroll
        for (int ks = 0; ks < 8; ks++) {
            const int kc = (ks << 3) + gl;
            uint32_t pa[4];
            pa[0] = __float_as_uint(Ps[qr * P_STRIDE + kc]);
            pa[1] = __float_as_uint(Ps[(qr + 8) * P_STRIDE + kc]);
            pa[2] = __float_as_uint(Ps[qr * P_STRIDE + kc + 4]);
            pa[3] = __float_as_uint(Ps[(qr + 8) * P_STRIDE + kc + 4]);
#pragma unroll
            for (int nj = 0; nj < 8; nj++) {
                const int d = (nj << 3) + gq;
                const uint32_t b0 = __float_as_uint(Vs[((ks << 3) + gl) * V_STRIDE + d]);
                const uint32_t b1 = __float_as_uint(Vs[((ks << 3) + gl + 4) * V_STRIDE + d]);
                mma_tf32(Oacc[nj], pa, b0, b1);
            }
        }

        __syncthreads();
        if (has_next) {
#pragma unroll
            for (int p = 0; p < 4; p++) {
                const int c = sC4 + (p << 4);
                *(float4*)&Ks[sRow * KS_STRIDE + c] = pk[p];
                *(float4*)&Vs[sRow * V_STRIDE + c] = pv[p];
            }
            __syncthreads();
        }
    }

    // Epilogue: rounded output (proj consumes via cp.async)
    const float inv0 = 1.0f / l0;
    const float inv1 = 1.0f / l1;
    const int n0 = q0 + qr;
    float* dst0 = &g_attn[((size_t)b * SEQ + n0) * DIMC + h * HDIM];
    float* dst1 = &g_attn[((size_t)b * SEQ + n0 + 8) * DIMC + h * HDIM];
#pragma unroll
    for (int nj = 0; nj < 8; nj++) {
        const int col = (nj << 3) + (gl << 1);
        *(float2*)(dst0 + col) = make_float2(f2tf32(Oacc[nj][0] * inv0),
                                             f2tf32(Oacc[nj][1] * inv0));
        *(float2*)(dst1 + col) = make_float2(f2tf32(Oacc[nj][2] * inv1),
                                             f2tf32(Oacc[nj][3] * inv1));
    }
}

// ---------------------------------------------------------------------------
extern "C" void kernel_launch(void* const* d_in, const int* in_sizes, int n_in,
                              void* d_out, int out_size)
{
    (void)in_sizes; (void)n_in; (void)out_size;
    const float* x      = (const float*)d_in[0];
    const float* w_qkv  = (const float*)d_in[1];
    const float* b_qkv  = (const float*)d_in[2];
    const float* w_proj = (const float*)d_in[3];
    const float* b_proj = (const float*)d_in[4];
    float* out = (float*)d_out;

    cudaFuncSetAttribute(mma_gemm<0>, cudaFuncAttributeMaxDynamicSharedMemorySize, GEMM_SMEM_BYTES);
    cudaFuncSetAttribute(mma_gemm<1>, cudaFuncAttributeMaxDynamicSharedMemorySize, GEMM_SMEM_BYTES);
    cudaFuncSetAttribute(attn_mma_kernel, cudaFuncAttributeMaxDynamicSharedMemorySize, ATTN_SMEM_BYTES);

    // 0) Pre-round inputs to tf32 (rna)
    round_tf32_kernel<<<1024, 256>>>((const float4*)x,      0, (int)((size_t)MROWS * DIMC / 4));
    round_tf32_kernel<<<2048, 256>>>((const float4*)w_qkv,  1, (int)((size_t)DIMC * 3 * DIMC / 4));
    round_tf32_kernel<<<1024, 256>>>((const float4*)w_proj, 2, (int)((size_t)DIMC * DIMC / 4));

    // 1) QKV GEMM: [4096,2560]@[2560,7680]+bias -> g_qkv (rounded, Q scaled)
    {
        dim3 grid(MROWS / 128, 3 * DIMC / 256);   // (32, 30)
        mma_gemm<0><<<grid, 256, GEMM_SMEM_BYTES>>>(b_qkv, nullptr);
    }
    // 2) Attention -> g_attn (rounded)
    {
        dim3 grid(SEQ / 128, NHEAD, BATCH);       // (16, 40, 2)
        attn_mma_kernel<<<grid, 256, ATTN_SMEM_BYTES>>>();
    }
    // 3) Projection: [4096,2560]@[2560,2560]+bias -> d_out (fp32)
    {
        dim3 grid(MROWS / 128, DIMC / 256);       // (32, 10)
        mma_gemm<1><<<grid, 256, GEMM_SMEM_BYTES>>>(b_proj, out);
    }
}

// round 12
// speedup vs baseline: 1.5893x; 1.0745x over previous
#include <cuda_runtime.h>
#include <cstdint>
#include <math.h>

#define DIMC    2560
#define NHEAD   40
#define HDIM    64
#define BATCH   2
#define SEQ     2048
#define MROWS   (BATCH * SEQ)
#define QKV_ONE ((size_t)BATCH * NHEAD * SEQ * HDIM)
#define ATTN_SCALE 0.125f

// Scratch (__device__ globals; allocation-free rule)
__device__ __align__(16) float g_qkv[3u * BATCH * NHEAD * SEQ * HDIM]; // tf32-rounded, Q pre-scaled
__device__ __align__(16) float g_attn[(size_t)MROWS * DIMC];           // tf32-rounded
__device__ __align__(16) float g_x[(size_t)MROWS * DIMC];
__device__ __align__(16) float g_wqkv[(size_t)DIMC * 3 * DIMC];
__device__ __align__(16) float g_wproj[(size_t)DIMC * DIMC];

// ---------------------------------------------------------------------------
__device__ __forceinline__ float f2tf32(float x) {
    uint32_t u;
    asm("cvt.rna.tf32.f32 %0, %1;" : "=r"(u) : "f"(x));
    return __uint_as_float(u);
}
__device__ __forceinline__ void mma_tf32(float* c, const uint32_t* a,
                                         uint32_t b0, uint32_t b1) {
    asm volatile(
        "mma.sync.aligned.m16n8k8.row.col.f32.tf32.tf32.f32 "
        "{%0,%1,%2,%3}, {%4,%5,%6,%7}, {%8,%9}, {%0,%1,%2,%3};"
        : "+f"(c[0]), "+f"(c[1]), "+f"(c[2]), "+f"(c[3])
        : "r"(a[0]), "r"(a[1]), "r"(a[2]), "r"(a[3]), "r"(b0), "r"(b1));
}
__device__ __forceinline__ uint32_t smem_u32(const void* p) {
    uint32_t a;
    asm("{ .reg .u64 t; cvta.to.shared.u64 t, %1; cvt.u32.u64 %0, t; }" : "=r"(a) : "l"(p));
    return a;
}
#define CP_ASYNC16(dst, src) \
    asm volatile("cp.async.cg.shared.global [%0], [%1], 16;" :: "r"(dst), "l"(src) : "memory")
#define CP_COMMIT() asm volatile("cp.async.commit_group;" ::: "memory")
#define CP_WAIT2()  asm volatile("cp.async.wait_group 2;" ::: "memory")
#define CP_WAIT0()  asm volatile("cp.async.wait_group 0;" ::: "memory")

// ---------------------------------------------------------------------------
// Pre-pass: tf32-round inputs into scratch. which: 0=x, 1=w_qkv, 2=w_proj
// ---------------------------------------------------------------------------
__global__ void round_tf32_kernel(const float4* __restrict__ src, int which, int n4)
{
    float4* dst = (which == 0) ? (float4*)g_x
                : (which == 1) ? (float4*)g_wqkv : (float4*)g_wproj;
    const int stride = gridDim.x * blockDim.x;
    for (int i = blockIdx.x * blockDim.x + threadIdx.x; i < n4; i += stride) {
        float4 v = src[i];
        v.x = f2tf32(v.x); v.y = f2tf32(v.y);
        v.z = f2tf32(v.z); v.w = f2tf32(v.w);
        dst[i] = v;
    }
}

// ---------------------------------------------------------------------------
// TF32 GEMM (FROZEN from R10: 819us QKV, tensor=64.7%)
// CTA 128x256, BK=32, 8 warps (64x64), 4-stage cp.async.
// ---------------------------------------------------------------------------
#define G_STAGE_FL 12288
#define GEMM_SMEM_BYTES (4 * G_STAGE_FL * 4)

template <int MODE>
__global__ __launch_bounds__(256, 1)
void mma_gemm(const float* __restrict__ bias, float* __restrict__ Oout)
{
    extern __shared__ float sm[];
    const uint32_t smb = smem_u32(sm);
    const int tid  = threadIdx.x;
    const int wid  = tid >> 5;
    const int lane = tid & 31;
    const int q    = lane >> 2;
    const int lp   = lane & 3;
    const int wm   = wid & 1;
    const int wn   = wid >> 1;
    const int bm   = blockIdx.x << 7;
    const int bn   = blockIdx.y << 8;
    const int K    = DIMC;
    const int nch  = K / 32;
    const int Nout = (MODE == 0) ? 3 * DIMC : DIMC;

    const float* Ag = (MODE == 0) ? g_x : g_attn;
    const float* W  = (MODE == 0) ? g_wqkv : g_wproj;

    const int lm  = tid >> 3;
    const int lc4 = (tid & 7) << 2;
    const uint32_t a_sw = (uint32_t)(lc4 ^ ((lm & 7) << 2));
    const int lk0 = tid >> 6;
    const int ln  = (tid & 63) << 2;
    const uint32_t b_sw = (uint32_t)(ln ^ (lk0 << 3));

    const float* Abase = Ag + (size_t)(bm + lm) * K + lc4;
    const float* Wbase = W + (size_t)lk0 * Nout + bn + ln;

    float acc[4][8][4];
#pragma unroll
    for (int mi = 0; mi < 4; mi++)
#pragma unroll
        for (int nj = 0; nj < 8; nj++)
#pragma unroll
            for (int r = 0; r < 4; r++) acc[mi][nj][r] = 0.0f;

#pragma unroll
    for (int s = 0; s < 3; s++) {
        const uint32_t sb = smb + (uint32_t)s * (G_STAGE_FL * 4);
        const int kc = s << 5;
#pragma unroll
        for (int p = 0; p < 4; p++)
            CP_ASYNC16(sb + ((((uint32_t)(lm + (p << 5))) << 5) + a_sw) * 4u,
                       Abase + kc + (size_t)(p << 5) * K);
#pragma unroll
        for (int p = 0; p < 8; p++)
            CP_ASYNC16(sb + 16384u + ((((uint32_t)(lk0 + (p << 2))) << 8) + b_sw) * 4u,
                       Wbase + (size_t)(kc + (p << 2)) * Nout);
        CP_COMMIT();
    }

    for (int c = 0; c < nch; c++) {
        CP_WAIT2();
        __syncthreads();
        if (c + 3 < nch) {
            const uint32_t sb = smb + (uint32_t)((c + 3) & 3) * (G_STAGE_FL * 4);
            const int kc = (c + 3) << 5;
#pragma unroll
            for (int p = 0; p < 4; p++)
                CP_ASYNC16(sb + ((((uint32_t)(lm + (p << 5))) << 5) + a_sw) * 4u,
                           Abase + kc + (size_t)(p << 5) * K);
#pragma unroll
            for (int p = 0; p < 8; p++)
                CP_ASYNC16(sb + 16384u + ((((uint32_t)(lk0 + (p << 2))) << 8) + b_sw) * 4u,
                           Wbase + (size_t)(kc + (p << 2)) * Nout);
        }
        CP_COMMIT();

        const float* As = sm + (c & 3) * G_STAGE_FL;
        const float* Bs = As + 4096;
#pragma unroll
        for (int ks = 0; ks < 4; ks++) {
            const int off0 = ((ks << 3) + lp) ^ (q << 2);
            const int off4 = off0 ^ 4;
            uint32_t a[4][4];
#pragma unroll
            for (int mi = 0; mi < 4; mi++) {
                const float* ap = As + (((wm << 6) + (mi << 4) + q) << 5);
                a[mi][0] = __float_as_uint(ap[off0]);
                a[mi][1] = __float_as_uint(ap[256 + off0]);
                a[mi][2] = __float_as_uint(ap[off4]);
                a[mi][3] = __float_as_uint(ap[256 + off4]);
            }
#pragma unroll
            for (int nj = 0; nj < 8; nj++) {
                const float* bp = Bs + (((ks << 3) + lp) << 8)
                                     + (wn << 6) + ((nj ^ lp) << 3) + q;
                const uint32_t b0 = __float_as_uint(bp[0]);
                const uint32_t b1 = __float_as_uint(bp[1024]);
#pragma unroll
                for (int mi = 0; mi < 4; mi++)
                    mma_tf32(acc[mi][nj], a[mi], b0, b1);
            }
        }
    }

#pragma unroll
    for (int mi = 0; mi < 4; mi++) {
        const int r0 = bm + (wm << 6) + (mi << 4) + q;
#pragma unroll
        for (int nj = 0; nj < 8; nj++) {
            const int col = bn + (wn << 6) + (nj << 3) + (lp << 1);
            const float bx = bias[col];
            const float by = bias[col + 1];
            if (MODE == 0) {
                const int which = col / DIMC;
                const int cc = col - which * DIMC;
                const int hh = cc >> 6;
                const int dd = cc & 63;
                const float sc = (which == 0) ? ATTN_SCALE : 1.0f;
                const int bb0 = r0 >> 11, nn0 = r0 & 2047;
                const int r1 = r0 + 8;
                const int bb1 = r1 >> 11, nn1 = r1 & 2047;
                const size_t base = (((size_t)which * BATCH) * NHEAD + hh) * SEQ * HDIM;
                float2 v0 = make_float2(f2tf32((acc[mi][nj][0] + bx) * sc),
                                        f2tf32((acc[mi][nj][1] + by) * sc));
                float2 v1 = make_float2(f2tf32((acc[mi][nj][2] + bx) * sc),
                                        f2tf32((acc[mi][nj][3] + by) * sc));
                *(float2*)&g_qkv[base + (((size_t)bb0 * NHEAD * SEQ) + nn0) * HDIM + dd] = v0;
                *(float2*)&g_qkv[base + (((size_t)bb1 * NHEAD * SEQ) + nn1) * HDIM + dd] = v1;
            } else {
                *(float2*)&Oout[(size_t)r0 * DIMC + col] =
                    make_float2(acc[mi][nj][0] + bx, acc[mi][nj][1] + by);
                *(float2*)&Oout[(size_t)(r0 + 8) * DIMC + col] =
                    make_float2(acc[mi][nj][2] + bx, acc[mi][nj][3] + by);
            }
        }
    }
}

// ---------------------------------------------------------------------------
// Flash attention v2: 128-key tiles (16 iters), cp.async double-buffered K/V,
// ONE __syncthreads per iteration. 8 warps x 16 q-rows (128-q CTA tile).
// Strides: K 68, V 72 (proven conflict-free), P 132 (== 68 mod 32).
// Smem: 2*(128*68 + 128*72)*4 + 128*132*4 = 210944 B.
// ---------------------------------------------------------------------------
#define KSTR2 68
#define VSTR2 72
#define PSTR2 132
#define OFFK0 0
#define OFFK1 (128 * KSTR2)               // 8704
#define OFFV0 (2 * 128 * KSTR2)           // 17408
#define OFFV1 (OFFV0 + 128 * VSTR2)       // 26624
#define OFFP  (OFFV0 + 2 * 128 * VSTR2)   // 35840
#define ATTN_SMEM_BYTES ((OFFP + 128 * PSTR2) * 4)  // 210944

__global__ __launch_bounds__(256, 1)
void attn_mma_kernel()
{
    extern __shared__ float sm[];
    const uint32_t smb = smem_u32(sm);
    float* Ps = sm + OFFP;

    const int tid  = threadIdx.x;
    const int wid  = tid >> 5;
    const int lane = tid & 31;
    const int gq   = lane >> 2;
    const int gl   = lane & 3;
    const int q0   = blockIdx.x << 7;
    const int h    = blockIdx.y;
    const int b    = blockIdx.z;

    const size_t bh = ((size_t)b * NHEAD + h) * ((size_t)SEQ * HDIM);
    const float* Qg = g_qkv + bh + ((size_t)q0 << 6);
    const float* Kg = g_qkv + QKV_ONE + bh;
    const float* Vg = g_qkv + 2 * QKV_ONE + bh;

    // Stage Q (pre-rounded, pre-scaled) -> Ps, then load register fragments
#pragma unroll
    for (int p = 0; p < 8; p++) {
        const int idx = tid + (p << 8);
        const int row = idx >> 4;
        const int c4  = (idx & 15) << 2;
        *(float4*)&Ps[row * PSTR2 + c4] = *(const float4*)(Qg + ((size_t)row << 6) + c4);
    }
    __syncthreads();

    const int qr = (wid << 4) + gq;
    uint32_t aq[8][4];
#pragma unroll
    for (int ks = 0; ks < 8; ks++) {
        const int kc = (ks << 3) + gl;
        aq[ks][0] = __float_as_uint(Ps[qr * PSTR2 + kc]);
        aq[ks][1] = __float_as_uint(Ps[(qr + 8) * PSTR2 + kc]);
        aq[ks][2] = __float_as_uint(Ps[qr * PSTR2 + kc + 4]);
        aq[ks][3] = __float_as_uint(Ps[(qr + 8) * PSTR2 + kc + 4]);
    }
    __syncthreads();   // Ps now free for P tiles

    // K/V staging mapping: 2048 float4 per matrix, 8 per thread
    const int sRow = tid >> 1;              // kernel-wide helper (rows via idx)
    (void)sRow;

    // Prologue: stage tile 0 into buffer 0
    {
#pragma unroll
        for (int p = 0; p < 8; p++) {
            const int idx = tid + (p << 8);
            const int row = idx >> 4;
            const int c4  = (idx & 15) << 2;
            CP_ASYNC16(smb + (uint32_t)((OFFK0 + row * KSTR2 + c4) << 2),
                       Kg + ((size_t)row << 6) + c4);
            CP_ASYNC16(smb + (uint32_t)((OFFV0 + row * VSTR2 + c4) << 2),
                       Vg + ((size_t)row << 6) + c4);
        }
        CP_COMMIT();
    }

    float Oacc[8][4];
#pragma unroll
    for (int nj = 0; nj < 8; nj++)
#pragma unroll
        for (int r = 0; r < 4; r++) Oacc[nj][r] = 0.0f;
    float m0 = -1e30f, m1 = -1e30f, l0 = 0.0f, l1 = 0.0f;

    for (int kt = 0; kt < SEQ / 128; kt++) {
        CP_WAIT0();
        __syncthreads();   // tile kt visible; all warps past compute of kt-1

        if (kt + 1 < SEQ / 128) {
            const int koff = ((kt + 1) & 1) ? OFFK1 : OFFK0;
            const int voff = ((kt + 1) & 1) ? OFFV1 : OFFV0;
            const float* Kt = Kg + (((size_t)(kt + 1)) << 7) * HDIM;
            const float* Vt = Vg + (((size_t)(kt + 1)) << 7) * HDIM;
#pragma unroll
            for (int p = 0; p < 8; p++) {
                const int idx = tid + (p << 8);
                const int row = idx >> 4;
                const int c4  = (idx & 15) << 2;
                CP_ASYNC16(smb + (uint32_t)((koff + row * KSTR2 + c4) << 2),
                           Kt + ((size_t)row << 6) + c4);
                CP_ASYNC16(smb + (uint32_t)((voff + row * VSTR2 + c4) << 2),
                           Vt + ((size_t)row << 6) + c4);
            }
        }
        CP_COMMIT();

        const float* Ks = sm + ((kt & 1) ? OFFK1 : OFFK0);
        const float* Vs = sm + ((kt & 1) ? OFFV1 : OFFV0);

        // ---- S = Q K^T : 16 n-tiles (128 keys) x 8 k-steps ----
        float s[16][4];
#pragma unroll
        for (int nj = 0; nj < 16; nj++) {
            s[nj][0] = 0.0f; s[nj][1] = 0.0f; s[nj][2] = 0.0f; s[nj][3] = 0.0f;
            const int nrow = (nj << 3) + gq;
#pragma unroll
            for (int ks = 0; ks < 8; ks++) {
                const int kc = (ks << 3) + gl;
                const uint32_t b0 = __float_as_uint(Ks[nrow * KSTR2 + kc]);
                const uint32_t b1 = __float_as_uint(Ks[nrow * KSTR2 + kc + 4]);
                mma_tf32(s[nj], aq[ks], b0, b1);
            }
        }

        // ---- Online softmax (quad reduce over lane bits 0,1) ----
        float c0 = -1e30f, c1 = -1e30f;
#pragma unroll
        for (int nj = 0; nj < 16; nj++) {
            c0 = fmaxf(c0, fmaxf(s[nj][0], s[nj][1]));
            c1 = fmaxf(c1, fmaxf(s[nj][2], s[nj][3]));
        }
        c0 = fmaxf(c0, __shfl_xor_sync(0xffffffffu, c0, 1));
        c0 = fmaxf(c0, __shfl_xor_sync(0xffffffffu, c0, 2));
        c1 = fmaxf(c1, __shfl_xor_sync(0xffffffffu, c1, 1));
        c1 = fmaxf(c1, __shfl_xor_sync(0xffffffffu, c1, 2));
        const float mn0 = fmaxf(m0, c0);
        const float mn1 = fmaxf(m1, c1);
        const float al0 = __expf(m0 - mn0);
        const float al1 = __expf(m1 - mn1);
        m0 = mn0; m1 = mn1;

        float r0 = 0.0f, r1 = 0.0f;
#pragma unroll
        for (int nj = 0; nj < 16; nj++) {
            s[nj][0] = __expf(s[nj][0] - mn0);
            s[nj][1] = __expf(s[nj][1] - mn0);
            s[nj][2] = __expf(s[nj][2] - mn1);
            s[nj][3] = __expf(s[nj][3] - mn1);
            r0 += s[nj][0] + s[nj][1];
            r1 += s[nj][2] + s[nj][3];
        }
        r0 += __shfl_xor_sync(0xffffffffu, r0, 1);
        r0 += __shfl_xor_sync(0xffffffffu, r0, 2);
        r1 += __shfl_xor_sync(0xffffffffu, r1, 1);
        r1 += __shfl_xor_sync(0xffffffffu, r1, 2);
        l0 = l0 * al0 + r0;
        l1 = l1 * al1 + r1;
#pragma unroll
        for (int nj = 0; nj < 8; nj++) {
            Oacc[nj][0] *= al0; Oacc[nj][1] *= al0;
            Oacc[nj][2] *= al1; Oacc[nj][3] *= al1;
        }

        // ---- P -> per-warp-private smem rows (qr, qr+8), tf32-rounded ----
#pragma unroll
        for (int nj = 0; nj < 16; nj++) {
            const int col = (nj << 3) + (gl << 1);
            *(float2*)&Ps[qr * PSTR2 + col] =
                make_float2(f2tf32(s[nj][0]), f2tf32(s[nj][1]));
            *(float2*)&Ps[(qr + 8) * PSTR2 + col] =
                make_float2(f2tf32(s[nj][2]), f2tf32(s[nj][3]));
        }
        __syncwarp();

        // ---- O += P V : 16 k-steps (128 keys) x 8 d-tiles ----
#pragma unroll
        for (int ks = 0; ks < 16; ks++) {
            const int kc = (ks << 3) + gl;
            uint32_t pa[4];
            pa[0] = __float_as_uint(Ps[qr * PSTR2 + kc]);
            pa[1] = __float_as_uint(Ps[(qr + 8) * PSTR2 + kc]);
            pa[2] = __float_as_uint(Ps[qr * PSTR2 + kc + 4]);
            pa[3] = __float_as_uint(Ps[(qr + 8) * PSTR2 + kc + 4]);
#pragma unroll
            for (int nj = 0; nj < 8; nj++) {
                const int d = (nj << 3) + gq;
                const uint32_t b0 = __float_as_uint(Vs[kc * VSTR2 + d]);
                const uint32_t b1 = __float_as_uint(Vs[(kc + 4) * VSTR2 + d]);
                mma_tf32(Oacc[nj], pa, b0, b1);
            }
        }
        // next iteration's top __syncthreads orders buffer reuse
    }

    // ---- Epilogue: normalize + tf32-round into g_attn ----
    const float inv0 = 1.0f / l0;
    const float inv1 = 1.0f / l1;
    const int n0 = q0 + qr;
    float* dst0 = &g_attn[((size_t)b * SEQ + n0) * DIMC + h * HDIM];
    float* dst1 = &g_attn[((size_t)b * SEQ + n0 + 8) * DIMC + h * HDIM];
#pragma unroll
    for (int nj = 0; nj < 8; nj++) {
        const int col = (nj << 3) + (gl << 1);
        *(float2*)(dst0 + col) = make_float2(f2tf32(Oacc[nj][0] * inv0),
                                             f2tf32(Oacc[nj][1] * inv0));
        *(float2*)(dst1 + col) = make_float2(f2tf32(Oacc[nj][2] * inv1),
                                             f2tf32(Oacc[nj][3] * inv1));
    }
}

// ---------------------------------------------------------------------------
extern "C" void kernel_launch(void* const* d_in, const int* in_sizes, int n_in,
                              void* d_out, int out_size)
{
    (void)in_sizes; (void)n_in; (void)out_size;
    const float* x      = (const float*)d_in[0];
    const float* w_qkv  = (const float*)d_in[1];
    const float* b_qkv  = (const float*)d_in[2];
    const float* w_proj = (const float*)d_in[3];
    const float* b_proj = (const float*)d_in[4];
    float* out = (float*)d_out;

    cudaFuncSetAttribute(mma_gemm<0>, cudaFuncAttributeMaxDynamicSharedMemorySize, GEMM_SMEM_BYTES);
    cudaFuncSetAttribute(mma_gemm<1>, cudaFuncAttributeMaxDynamicSharedMemorySize, GEMM_SMEM_BYTES);
    cudaFuncSetAttribute(attn_mma_kernel, cudaFuncAttributeMaxDynamicSharedMemorySize, ATTN_SMEM_BYTES);

    // 0) Pre-round inputs to tf32 (rna)
    round_tf32_kernel<<<1024, 256>>>((const float4*)x,      0, (int)((size_t)MROWS * DIMC / 4));
    round_tf32_kernel<<<2048, 256>>>((const float4*)w_qkv,  1, (int)((size_t)DIMC * 3 * DIMC / 4));
    round_tf32_kernel<<<1024, 256>>>((const float4*)w_proj, 2, (int)((size_t)DIMC * DIMC / 4));

    // 1) QKV GEMM -> g_qkv (rounded, Q pre-scaled)
    {
        dim3 grid(MROWS / 128, 3 * DIMC / 256);
        mma_gemm<0><<<grid, 256, GEMM_SMEM_BYTES>>>(b_qkv, nullptr);
    }
    // 2) Attention -> g_attn (rounded)
    {
        dim3 grid(SEQ / 128, NHEAD, BATCH);     // (16, 40, 2)
        attn_mma_kernel<<<grid, 256, ATTN_SMEM_BYTES>>>();
    }
    // 3) Projection -> d_out (fp32)
    {
        dim3 grid(MROWS / 128, DIMC / 256);
        mma_gemm<1><<<grid, 256, GEMM_SMEM_BYTES>>>(b_proj, out);
    }
}

// round 13
// speedup vs baseline: 1.6229x; 1.0212x over previous
#include <cuda_runtime.h>
#include <cstdint>
#include <math.h>

#define DIMC    2560
#define NHEAD   40
#define HDIM    64
#define BATCH   2
#define SEQ     2048
#define MROWS   (BATCH * SEQ)
#define QKV_ONE ((size_t)BATCH * NHEAD * SEQ * HDIM)
#define ATTN_SCALE 0.125f

// Scratch (__device__ globals; allocation-free rule)
__device__ __align__(16) float g_qkv[3u * BATCH * NHEAD * SEQ * HDIM]; // tf32-rounded, Q pre-scaled
__device__ __align__(16) float g_attn[(size_t)MROWS * DIMC];           // tf32-rounded
__device__ __align__(16) float g_x[(size_t)MROWS * DIMC];
__device__ __align__(16) float g_wqkv[(size_t)DIMC * 3 * DIMC];
__device__ __align__(16) float g_wproj[(size_t)DIMC * DIMC];

// ---------------------------------------------------------------------------
__device__ __forceinline__ float f2tf32(float x) {
    uint32_t u;
    asm("cvt.rna.tf32.f32 %0, %1;" : "=r"(u) : "f"(x));
    return __uint_as_float(u);
}
__device__ __forceinline__ void mma_tf32(float* c, const uint32_t* a,
                                         uint32_t b0, uint32_t b1) {
    asm volatile(
        "mma.sync.aligned.m16n8k8.row.col.f32.tf32.tf32.f32 "
        "{%0,%1,%2,%3}, {%4,%5,%6,%7}, {%8,%9}, {%0,%1,%2,%3};"
        : "+f"(c[0]), "+f"(c[1]), "+f"(c[2]), "+f"(c[3])
        : "r"(a[0]), "r"(a[1]), "r"(a[2]), "r"(a[3]), "r"(b0), "r"(b1));
}
__device__ __forceinline__ uint32_t smem_u32(const void* p) {
    uint32_t a;
    asm("{ .reg .u64 t; cvta.to.shared.u64 t, %1; cvt.u32.u64 %0, t; }" : "=r"(a) : "l"(p));
    return a;
}
#define CP_ASYNC16(dst, src) \
    asm volatile("cp.async.cg.shared.global [%0], [%1], 16;" :: "r"(dst), "l"(src) : "memory")
#define CP_COMMIT() asm volatile("cp.async.commit_group;" ::: "memory")
#define CP_WAIT1()  asm volatile("cp.async.wait_group 1;" ::: "memory")
#define CP_WAIT0()  asm volatile("cp.async.wait_group 0;" ::: "memory")

// ---------------------------------------------------------------------------
// Pre-pass: tf32-round inputs into scratch. which: 0=x, 1=w_qkv, 2=w_proj
// ---------------------------------------------------------------------------
__global__ void round_tf32_kernel(const float4* __restrict__ src, int which, int n4)
{
    float4* dst = (which == 0) ? (float4*)g_x
                : (which == 1) ? (float4*)g_wqkv : (float4*)g_wproj;
    const int stride = gridDim.x * blockDim.x;
    for (int i = blockIdx.x * blockDim.x + threadIdx.x; i < n4; i += stride) {
        float4 v = src[i];
        v.x = f2tf32(v.x); v.y = f2tf32(v.y);
        v.z = f2tf32(v.z); v.w = f2tf32(v.w);
        dst[i] = v;
    }
}

// ---------------------------------------------------------------------------
// TF32 GEMM v2: CTA 128x128, BK=32, 3-stage cp.async, 2 CTAs/SM.
// 8 warps, warp tile 64x32 (wm = wid&1: 64-row strip, wn = wid>>1: 32-col strip).
// A stage: As[m][k ^ 4*(m&7)]  (128x32 fl); B stage: Bs[k][n ^ 8*(k&3)] (32x128 fl).
// Stage = 8192 floats = 32KB; 3 stages = 96KB -> two CTAs co-resident.
// ---------------------------------------------------------------------------
#define G_STAGE_FL 8192
#define GEMM_SMEM_BYTES (3 * G_STAGE_FL * 4)   // 98304

template <int MODE>
__global__ __launch_bounds__(256, 2)
void mma_gemm(const float* __restrict__ bias, float* __restrict__ Oout)
{
    extern __shared__ float sm[];
    const uint32_t smb = smem_u32(sm);
    const int tid  = threadIdx.x;
    const int wid  = tid >> 5;
    const int lane = tid & 31;
    const int q    = lane >> 2;
    const int lp   = lane & 3;
    const int wm   = wid & 1;        // 64-row strip
    const int wn   = wid >> 1;       // 32-col strip (0..3)
    const int bm   = blockIdx.x << 7;
    const int bn   = blockIdx.y << 7;
    const int K    = DIMC;
    const int nch  = K / 32;         // 80
    const int Nout = (MODE == 0) ? 3 * DIMC : DIMC;

    const float* Ag = (MODE == 0) ? g_x : g_attn;
    const float* W  = (MODE == 0) ? g_wqkv : g_wproj;

    // A loader: 4 float4/thread. rows lm (+32/p), k-chunk lc4; swizzle k^4*(m&7)
    const int lm  = tid >> 3;
    const int lc4 = (tid & 7) << 2;
    const uint32_t a_sw = (uint32_t)(lc4 ^ ((lm & 7) << 2));
    // B loader: 4 float4/thread. rows k = lk0 (+8/p), n-chunk ln; swizzle n^8*(k&3)
    const int lk0 = tid >> 5;                      // 0..7
    const int ln  = (tid & 31) << 2;               // 0..124
    const uint32_t b_sw = (uint32_t)(ln ^ ((lk0 & 3) << 3));

    const float* Abase = Ag + (size_t)(bm + lm) * K + lc4;
    const float* Wbase = W + (size_t)lk0 * Nout + bn + ln;

    float acc[4][4][4];
#pragma unroll
    for (int mi = 0; mi < 4; mi++)
#pragma unroll
        for (int nj = 0; nj < 4; nj++)
#pragma unroll
            for (int r = 0; r < 4; r++) acc[mi][nj][r] = 0.0f;

#pragma unroll
    for (int s = 0; s < 2; s++) {      // prologue: stages 0,1
        const uint32_t sb = smb + (uint32_t)s * (G_STAGE_FL * 4);
        const int kc = s << 5;
#pragma unroll
        for (int p = 0; p < 4; p++)
            CP_ASYNC16(sb + ((((uint32_t)(lm + (p << 5))) << 5) + a_sw) * 4u,
                       Abase + kc + (size_t)(p << 5) * K);
#pragma unroll
        for (int p = 0; p < 4; p++)
            CP_ASYNC16(sb + 16384u + ((((uint32_t)(lk0 + (p << 3))) << 7) + b_sw) * 4u,
                       Wbase + (size_t)(kc + (p << 3)) * Nout);
        CP_COMMIT();
    }

    for (int c = 0; c < nch; c++) {
        CP_WAIT1();          // stage c resident (c+1 may still be in flight)
        __syncthreads();     // also: all warps done computing chunk c-1
        if (c + 2 < nch) {   // stage c+2 -> buffer (c+2)%3 (not in use)
            const uint32_t sb = smb + (uint32_t)((c + 2) % 3) * (G_STAGE_FL * 4);
            const int kc = (c + 2) << 5;
#pragma unroll
            for (int p = 0; p < 4; p++)
                CP_ASYNC16(sb + ((((uint32_t)(lm + (p << 5))) << 5) + a_sw) * 4u,
                           Abase + kc + (size_t)(p << 5) * K);
#pragma unroll
            for (int p = 0; p < 4; p++)
                CP_ASYNC16(sb + 16384u + ((((uint32_t)(lk0 + (p << 3))) << 7) + b_sw) * 4u,
                           Wbase + (size_t)(kc + (p << 3)) * Nout);
        }
        CP_COMMIT();         // empty group at tail keeps wait-count semantics

        const float* As = sm + (c % 3) * G_STAGE_FL;
        const float* Bs = As + 4096;
#pragma unroll
        for (int ks = 0; ks < 4; ks++) {
            const int kcol = (ks << 3) + lp;
            const int off0 = kcol ^ (q << 2);
            const int off4 = off0 ^ 4;
            uint32_t a[4][4];
#pragma unroll
            for (int mi = 0; mi < 4; mi++) {
                const float* ap = As + (((wm << 6) + (mi << 4) + q) << 5);
                a[mi][0] = __float_as_uint(ap[off0]);
                a[mi][1] = __float_as_uint(ap[256 + off0]);
                a[mi][2] = __float_as_uint(ap[off4]);
                a[mi][3] = __float_as_uint(ap[256 + off4]);
            }
#pragma unroll
            for (int nj = 0; nj < 4; nj++) {
                const float* bp = Bs + (kcol << 7)
                                     + (wn << 5) + ((nj ^ lp) << 3) + q;
                const uint32_t b0 = __float_as_uint(bp[0]);
                const uint32_t b1 = __float_as_uint(bp[512]);
#pragma unroll
                for (int mi = 0; mi < 4; mi++)
                    mma_tf32(acc[mi][nj], a[mi], b0, b1);
            }
        }
    }

    // Epilogue: c0,c1 -> row r0 cols 2lp,2lp+1 ; c2,c3 -> row r0+8
#pragma unroll
    for (int mi = 0; mi < 4; mi++) {
        const int r0 = bm + (wm << 6) + (mi << 4) + q;
#pragma unroll
        for (int nj = 0; nj < 4; nj++) {
            const int col = bn + (wn << 5) + (nj << 3) + (lp << 1);
            const float bx = bias[col];
            const float by = bias[col + 1];
            if (MODE == 0) {
                const int which = col / DIMC;
                const int cc = col - which * DIMC;
                const int hh = cc >> 6;
                const int dd = cc & 63;
                const float sc = (which == 0) ? ATTN_SCALE : 1.0f;
                const int bb0 = r0 >> 11, nn0 = r0 & 2047;
                const int r1 = r0 + 8;
                const int bb1 = r1 >> 11, nn1 = r1 & 2047;
                const size_t base = (((size_t)which * BATCH) * NHEAD + hh) * SEQ * HDIM;
                float2 v0 = make_float2(f2tf32((acc[mi][nj][0] + bx) * sc),
                                        f2tf32((acc[mi][nj][1] + by) * sc));
                float2 v1 = make_float2(f2tf32((acc[mi][nj][2] + bx) * sc),
                                        f2tf32((acc[mi][nj][3] + by) * sc));
                *(float2*)&g_qkv[base + (((size_t)bb0 * NHEAD * SEQ) + nn0) * HDIM + dd] = v0;
                *(float2*)&g_qkv[base + (((size_t)bb1 * NHEAD * SEQ) + nn1) * HDIM + dd] = v1;
            } else {
                *(float2*)&Oout[(size_t)r0 * DIMC + col] =
                    make_float2(acc[mi][nj][0] + bx, acc[mi][nj][1] + by);
                *(float2*)&Oout[(size_t)(r0 + 8) * DIMC + col] =
                    make_float2(acc[mi][nj][2] + bx, acc[mi][nj][3] + by);
            }
        }
    }
}

// ---------------------------------------------------------------------------
// Flash attention (FROZEN from R11): 128-key tiles, cp.async double-buffered,
// one __syncthreads per iteration.
// ---------------------------------------------------------------------------
#define KSTR2 68
#define VSTR2 72
#define PSTR2 132
#define OFFK0 0
#define OFFK1 (128 * KSTR2)
#define OFFV0 (2 * 128 * KSTR2)
#define OFFV1 (OFFV0 + 128 * VSTR2)
#define OFFP  (OFFV0 + 2 * 128 * VSTR2)
#define ATTN_SMEM_BYTES ((OFFP + 128 * PSTR2) * 4)  // 210944

__global__ __launch_bounds__(256, 1)
void attn_mma_kernel()
{
    extern __shared__ float sm[];
    const uint32_t smb = smem_u32(sm);
    float* Ps = sm + OFFP;

    const int tid  = threadIdx.x;
    const int wid  = tid >> 5;
    const int lane = tid & 31;
    const int gq   = lane >> 2;
    const int gl   = lane & 3;
    const int q0   = blockIdx.x << 7;
    const int h    = blockIdx.y;
    const int b    = blockIdx.z;

    const size_t bh = ((size_t)b * NHEAD + h) * ((size_t)SEQ * HDIM);
    const float* Qg = g_qkv + bh + ((size_t)q0 << 6);
    const float* Kg = g_qkv + QKV_ONE + bh;
    const float* Vg = g_qkv + 2 * QKV_ONE + bh;

#pragma unroll
    for (int p = 0; p < 8; p++) {
        const int idx = tid + (p << 8);
        const int row = idx >> 4;
        const int c4  = (idx & 15) << 2;
        *(float4*)&Ps[row * PSTR2 + c4] = *(const float4*)(Qg + ((size_t)row << 6) + c4);
    }
    __syncthreads();

    const int qr = (wid << 4) + gq;
    uint32_t aq[8][4];
#pragma unroll
    for (int ks = 0; ks < 8; ks++) {
        const int kc = (ks << 3) + gl;
        aq[ks][0] = __float_as_uint(Ps[qr * PSTR2 + kc]);
        aq[ks][1] = __float_as_uint(Ps[(qr + 8) * PSTR2 + kc]);
        aq[ks][2] = __float_as_uint(Ps[qr * PSTR2 + kc + 4]);
        aq[ks][3] = __float_as_uint(Ps[(qr + 8) * PSTR2 + kc + 4]);
    }
    __syncthreads();

    {
#pragma unroll
        for (int p = 0; p < 8; p++) {
            const int idx = tid + (p << 8);
            const int row = idx >> 4;
            const int c4  = (idx & 15) << 2;
            CP_ASYNC16(smb + (uint32_t)((OFFK0 + row * KSTR2 + c4) << 2),
                       Kg + ((size_t)row << 6) + c4);
            CP_ASYNC16(smb + (uint32_t)((OFFV0 + row * VSTR2 + c4) << 2),
                       Vg + ((size_t)row << 6) + c4);
        }
        CP_COMMIT();
    }

    float Oacc[8][4];
#pragma unroll
    for (int nj = 0; nj < 8; nj++)
#pragma unroll
        for (int r = 0; r < 4; r++) Oacc[nj][r] = 0.0f;
    float m0 = -1e30f, m1 = -1e30f, l0 = 0.0f, l1 = 0.0f;

    for (int kt = 0; kt < SEQ / 128; kt++) {
        CP_WAIT0();
        __syncthreads();

        if (kt + 1 < SEQ / 128) {
            const int koff = ((kt + 1) & 1) ? OFFK1 : OFFK0;
            const int voff = ((kt + 1) & 1) ? OFFV1 : OFFV0;
            const float* Kt = Kg + (((size_t)(kt + 1)) << 7) * HDIM;
            const float* Vt = Vg + (((size_t)(kt + 1)) << 7) * HDIM;
#pragma unroll
            for (int p = 0; p < 8; p++) {
                const int idx = tid + (p << 8);
                const int row = idx >> 4;
                const int c4  = (idx & 15) << 2;
                CP_ASYNC16(smb + (uint32_t)((koff + row * KSTR2 + c4) << 2),
                           Kt + ((size_t)row << 6) + c4);
                CP_ASYNC16(smb + (uint32_t)((voff + row * VSTR2 + c4) << 2),
                           Vt + ((size_t)row << 6) + c4);
            }
        }
        CP_COMMIT();

        const float* Ks = sm + ((kt & 1) ? OFFK1 : OFFK0);
        const float* Vs = sm + ((kt & 1) ? OFFV1 : OFFV0);

        float s[16][4];
#pragma unroll
        for (int nj = 0; nj < 16; nj++) {
            s[nj][0] = 0.0f; s[nj][1] = 0.0f; s[nj][2] = 0.0f; s[nj][3] = 0.0f;
            const int nrow = (nj << 3) + gq;
#pragma unroll
            for (int ks = 0; ks < 8; ks++) {
                const int kc = (ks << 3) + gl;
                const uint32_t b0 = __float_as_uint(Ks[nrow * KSTR2 + kc]);
                const uint32_t b1 = __float_as_uint(Ks[nrow * KSTR2 + kc + 4]);
                mma_tf32(s[nj], aq[ks], b0, b1);
            }
        }

        float c0 = -1e30f, c1 = -1e30f;
#pragma unroll
        for (int nj = 0; nj < 16; nj++) {
            c0 = fmaxf(c0, fmaxf(s[nj][0], s[nj][1]));
            c1 = fmaxf(c1, fmaxf(s[nj][2], s[nj][3]));
        }
        c0 = fmaxf(c0, __shfl_xor_sync(0xffffffffu, c0, 1));
        c0 = fmaxf(c0, __shfl_xor_sync(0xffffffffu, c0, 2));
        c1 = fmaxf(c1, __shfl_xor_sync(0xffffffffu, c1, 1));
        c1 = fmaxf(c1, __shfl_xor_sync(0xffffffffu, c1, 2));
        const float mn0 = fmaxf(m0, c0);
        const float mn1 = fmaxf(m1, c1);
        const float al0 = __expf(m0 - mn0);
        const float al1 = __expf(m1 - mn1);
        m0 = mn0; m1 = mn1;

        float r0 = 0.0f, r1 = 0.0f;
#pragma unroll
        for (int nj = 0; nj < 16; nj++) {
            s[nj][0] = __expf(s[nj][0] - mn0);
            s[nj][1] = __expf(s[nj][1] - mn0);
            s[nj][2] = __expf(s[nj][2] - mn1);
            s[nj][3] = __expf(s[nj][3] - mn1);
            r0 += s[nj][0] + s[nj][1];
            r1 += s[nj][2] + s[nj][3];
        }
        r0 += __shfl_xor_sync(0xffffffffu, r0, 1);
        r0 += __shfl_xor_sync(0xffffffffu, r0, 2);
        r1 += __shfl_xor_sync(0xffffffffu, r1, 1);
        r1 += __shfl_xor_sync(0xffffffffu, r1, 2);
        l0 = l0 * al0 + r0;
        l1 = l1 * al1 + r1;
#pragma unroll
        for (int nj = 0; nj < 8; nj++) {
            Oacc[nj][0] *= al0; Oacc[nj][1] *= al0;
            Oacc[nj][2] *= al1; Oacc[nj][3] *= al1;
        }

#pragma unroll
        for (int nj = 0; nj < 16; nj++) {
            const int col = (nj << 3) + (gl << 1);
            *(float2*)&Ps[qr * PSTR2 + col] =
                make_float2(f2tf32(s[nj][0]), f2tf32(s[nj][1]));
            *(float2*)&Ps[(qr + 8) * PSTR2 + col] =
                make_float2(f2tf32(s[nj][2]), f2tf32(s[nj][3]));
        }
        __syncwarp();

#pragma unroll
        for (int ks = 0; ks < 16; ks++) {
            const int kc = (ks << 3) + gl;
            uint32_t pa[4];
            pa[0] = __float_as_uint(Ps[qr * PSTR2 + kc]);
            pa[1] = __float_as_uint(Ps[(qr + 8) * PSTR2 + kc]);
            pa[2] = __float_as_uint(Ps[qr * PSTR2 + kc + 4]);
            pa[3] = __float_as_uint(Ps[(qr + 8) * PSTR2 + kc + 4]);
#pragma unroll
            for (int nj = 0; nj < 8; nj++) {
                const int d = (nj << 3) + gq;
                const uint32_t b0 = __float_as_uint(Vs[kc * VSTR2 + d]);
                const uint32_t b1 = __float_as_uint(Vs[(kc + 4) * VSTR2 + d]);
                mma_tf32(Oacc[nj], pa, b0, b1);
            }
        }
    }

    const float inv0 = 1.0f / l0;
    const float inv1 = 1.0f / l1;
    const int n0 = q0 + qr;
    float* dst0 = &g_attn[((size_t)b * SEQ + n0) * DIMC + h * HDIM];
    float* dst1 = &g_attn[((size_t)b * SEQ + n0 + 8) * DIMC + h * HDIM];
#pragma unroll
    for (int nj = 0; nj < 8; nj++) {
        const int col = (nj << 3) + (gl << 1);
        *(float2*)(dst0 + col) = make_float2(f2tf32(Oacc[nj][0] * inv0),
                                             f2tf32(Oacc[nj][1] * inv0));
        *(float2*)(dst1 + col) = make_float2(f2tf32(Oacc[nj][2] * inv1),
                                             f2tf32(Oacc[nj][3] * inv1));
    }
}

// ---------------------------------------------------------------------------
extern "C" void kernel_launch(void* const* d_in, const int* in_sizes, int n_in,
                              void* d_out, int out_size)
{
    (void)in_sizes; (void)n_in; (void)out_size;
    const float* x      = (const float*)d_in[0];
    const float* w_qkv  = (const float*)d_in[1];
    const float* b_qkv  = (const float*)d_in[2];
    const float* w_proj = (const float*)d_in[3];
    const float* b_proj = (const float*)d_in[4];
    float* out = (float*)d_out;

    cudaFuncSetAttribute(mma_gemm<0>, cudaFuncAttributeMaxDynamicSharedMemorySize, GEMM_SMEM_BYTES);
    cudaFuncSetAttribute(mma_gemm<1>, cudaFuncAttributeMaxDynamicSharedMemorySize, GEMM_SMEM_BYTES);
    cudaFuncSetAttribute(attn_mma_kernel, cudaFuncAttributeMaxDynamicSharedMemorySize, ATTN_SMEM_BYTES);

    // 0) Pre-round inputs to tf32 (rna)
    round_tf32_kernel<<<1024, 256>>>((const float4*)x,      0, (int)((size_t)MROWS * DIMC / 4));
    round_tf32_kernel<<<2048, 256>>>((const float4*)w_qkv,  1, (int)((size_t)DIMC * 3 * DIMC / 4));
    round_tf32_kernel<<<1024, 256>>>((const float4*)w_proj, 2, (int)((size_t)DIMC * DIMC / 4));

    // 1) QKV GEMM -> g_qkv (rounded, Q pre-scaled)
    {
        dim3 grid(MROWS / 128, 3 * DIMC / 128);   // (32, 60)
        mma_gemm<0><<<grid, 256, GEMM_SMEM_BYTES>>>(b_qkv, nullptr);
    }
    // 2) Attention -> g_attn (rounded)
    {
        dim3 grid(SEQ / 128, NHEAD, BATCH);       // (16, 40, 2)
        attn_mma_kernel<<<grid, 256, ATTN_SMEM_BYTES>>>();
    }
    // 3) Projection -> d_out (fp32)
    {
        dim3 grid(MROWS / 128, DIMC / 128);       // (32, 20)
        mma_gemm<1><<<grid, 256, GEMM_SMEM_BYTES>>>(b_proj, out);
    }
}

// round 14
// speedup vs baseline: 1.6293x; 1.0039x over previous
#include <cuda_runtime.h>
#include <cstdint>
#include <math.h>

#define DIMC    2560
#define NHEAD   40
#define HDIM    64
#define BATCH   2
#define SEQ     2048
#define MROWS   (BATCH * SEQ)
#define QKV_ONE ((size_t)BATCH * NHEAD * SEQ * HDIM)
#define ATTN_SCALE 0.125f

// Scratch (__device__ globals; allocation-free rule)
__device__ __align__(16) float g_qkv[3u * BATCH * NHEAD * SEQ * HDIM]; // tf32-rounded, Q pre-scaled
__device__ __align__(16) float g_attn[(size_t)MROWS * DIMC];           // tf32-rounded
__device__ __align__(16) float g_x[(size_t)MROWS * DIMC];
__device__ __align__(16) float g_wqkv[(size_t)DIMC * 3 * DIMC];
__device__ __align__(16) float g_wproj[(size_t)DIMC * DIMC];

// ---------------------------------------------------------------------------
__device__ __forceinline__ float f2tf32(float x) {
    uint32_t u;
    asm("cvt.rna.tf32.f32 %0, %1;" : "=r"(u) : "f"(x));
    return __uint_as_float(u);
}
__device__ __forceinline__ void mma_tf32(float* c, const uint32_t* a,
                                         uint32_t b0, uint32_t b1) {
    asm volatile(
        "mma.sync.aligned.m16n8k8.row.col.f32.tf32.tf32.f32 "
        "{%0,%1,%2,%3}, {%4,%5,%6,%7}, {%8,%9}, {%0,%1,%2,%3};"
        : "+f"(c[0]), "+f"(c[1]), "+f"(c[2]), "+f"(c[3])
        : "r"(a[0]), "r"(a[1]), "r"(a[2]), "r"(a[3]), "r"(b0), "r"(b1));
}
__device__ __forceinline__ uint32_t smem_u32(const void* p) {
    uint32_t a;
    asm("{ .reg .u64 t; cvta.to.shared.u64 t, %1; cvt.u32.u64 %0, t; }" : "=r"(a) : "l"(p));
    return a;
}
#define CP_ASYNC16(dst, src) \
    asm volatile("cp.async.cg.shared.global [%0], [%1], 16;" :: "r"(dst), "l"(src) : "memory")
#define CP_COMMIT() asm volatile("cp.async.commit_group;" ::: "memory")
#define CP_WAIT1()  asm volatile("cp.async.wait_group 1;" ::: "memory")
#define CP_WAIT0()  asm volatile("cp.async.wait_group 0;" ::: "memory")

// ---------------------------------------------------------------------------
// Pre-pass: tf32-round inputs into scratch. which: 0=x, 1=w_qkv, 2=w_proj
// ---------------------------------------------------------------------------
__global__ void round_tf32_kernel(const float4* __restrict__ src, int which, int n4)
{
    float4* dst = (which == 0) ? (float4*)g_x
                : (which == 1) ? (float4*)g_wqkv : (float4*)g_wproj;
    const int stride = gridDim.x * blockDim.x;
    for (int i = blockIdx.x * blockDim.x + threadIdx.x; i < n4; i += stride) {
        float4 v = src[i];
        v.x = f2tf32(v.x); v.y = f2tf32(v.y);
        v.z = f2tf32(v.z); v.w = f2tf32(v.w);
        dst[i] = v;
    }
}

// ---------------------------------------------------------------------------
// TF32 GEMM (FROZEN from R12: 812us QKV; at mma.sync issue ceiling)
// CTA 128x128, BK=32, 3-stage cp.async, 2 CTAs/SM, warp tile 64x32.
// ---------------------------------------------------------------------------
#define G_STAGE_FL 8192
#define GEMM_SMEM_BYTES (3 * G_STAGE_FL * 4)   // 98304

template <int MODE>
__global__ __launch_bounds__(256, 2)
void mma_gemm(const float* __restrict__ bias, float* __restrict__ Oout)
{
    extern __shared__ float sm[];
    const uint32_t smb = smem_u32(sm);
    const int tid  = threadIdx.x;
    const int wid  = tid >> 5;
    const int lane = tid & 31;
    const int q    = lane >> 2;
    const int lp   = lane & 3;
    const int wm   = wid & 1;
    const int wn   = wid >> 1;
    const int bm   = blockIdx.x << 7;
    const int bn   = blockIdx.y << 7;
    const int K    = DIMC;
    const int nch  = K / 32;
    const int Nout = (MODE == 0) ? 3 * DIMC : DIMC;

    const float* Ag = (MODE == 0) ? g_x : g_attn;
    const float* W  = (MODE == 0) ? g_wqkv : g_wproj;

    const int lm  = tid >> 3;
    const int lc4 = (tid & 7) << 2;
    const uint32_t a_sw = (uint32_t)(lc4 ^ ((lm & 7) << 2));
    const int lk0 = tid >> 5;
    const int ln  = (tid & 31) << 2;
    const uint32_t b_sw = (uint32_t)(ln ^ ((lk0 & 3) << 3));

    const float* Abase = Ag + (size_t)(bm + lm) * K + lc4;
    const float* Wbase = W + (size_t)lk0 * Nout + bn + ln;

    float acc[4][4][4];
#pragma unroll
    for (int mi = 0; mi < 4; mi++)
#pragma unroll
        for (int nj = 0; nj < 4; nj++)
#pragma unroll
            for (int r = 0; r < 4; r++) acc[mi][nj][r] = 0.0f;

#pragma unroll
    for (int s = 0; s < 2; s++) {
        const uint32_t sb = smb + (uint32_t)s * (G_STAGE_FL * 4);
        const int kc = s << 5;
#pragma unroll
        for (int p = 0; p < 4; p++)
            CP_ASYNC16(sb + ((((uint32_t)(lm + (p << 5))) << 5) + a_sw) * 4u,
                       Abase + kc + (size_t)(p << 5) * K);
#pragma unroll
        for (int p = 0; p < 4; p++)
            CP_ASYNC16(sb + 16384u + ((((uint32_t)(lk0 + (p << 3))) << 7) + b_sw) * 4u,
                       Wbase + (size_t)(kc + (p << 3)) * Nout);
        CP_COMMIT();
    }

    for (int c = 0; c < nch; c++) {
        CP_WAIT1();
        __syncthreads();
        if (c + 2 < nch) {
            const uint32_t sb = smb + (uint32_t)((c + 2) % 3) * (G_STAGE_FL * 4);
            const int kc = (c + 2) << 5;
#pragma unroll
            for (int p = 0; p < 4; p++)
                CP_ASYNC16(sb + ((((uint32_t)(lm + (p << 5))) << 5) + a_sw) * 4u,
                           Abase + kc + (size_t)(p << 5) * K);
#pragma unroll
            for (int p = 0; p < 4; p++)
                CP_ASYNC16(sb + 16384u + ((((uint32_t)(lk0 + (p << 3))) << 7) + b_sw) * 4u,
                           Wbase + (size_t)(kc + (p << 3)) * Nout);
        }
        CP_COMMIT();

        const float* As = sm + (c % 3) * G_STAGE_FL;
        const float* Bs = As + 4096;
#pragma unroll
        for (int ks = 0; ks < 4; ks++) {
            const int kcol = (ks << 3) + lp;
            const int off0 = kcol ^ (q << 2);
            const int off4 = off0 ^ 4;
            uint32_t a[4][4];
#pragma unroll
            for (int mi = 0; mi < 4; mi++) {
                const float* ap = As + (((wm << 6) + (mi << 4) + q) << 5);
                a[mi][0] = __float_as_uint(ap[off0]);
                a[mi][1] = __float_as_uint(ap[256 + off0]);
                a[mi][2] = __float_as_uint(ap[off4]);
                a[mi][3] = __float_as_uint(ap[256 + off4]);
            }
#pragma unroll
            for (int nj = 0; nj < 4; nj++) {
                const float* bp = Bs + (kcol << 7)
                                     + (wn << 5) + ((nj ^ lp) << 3) + q;
                const uint32_t b0 = __float_as_uint(bp[0]);
                const uint32_t b1 = __float_as_uint(bp[512]);
#pragma unroll
                for (int mi = 0; mi < 4; mi++)
                    mma_tf32(acc[mi][nj], a[mi], b0, b1);
            }
        }
    }

#pragma unroll
    for (int mi = 0; mi < 4; mi++) {
        const int r0 = bm + (wm << 6) + (mi << 4) + q;
#pragma unroll
        for (int nj = 0; nj < 4; nj++) {
            const int col = bn + (wn << 5) + (nj << 3) + (lp << 1);
            const float bx = bias[col];
            const float by = bias[col + 1];
            if (MODE == 0) {
                const int which = col / DIMC;
                const int cc = col - which * DIMC;
                const int hh = cc >> 6;
                const int dd = cc & 63;
                const float sc = (which == 0) ? ATTN_SCALE : 1.0f;
                const int bb0 = r0 >> 11, nn0 = r0 & 2047;
                const int r1 = r0 + 8;
                const int bb1 = r1 >> 11, nn1 = r1 & 2047;
                const size_t base = (((size_t)which * BATCH) * NHEAD + hh) * SEQ * HDIM;
                float2 v0 = make_float2(f2tf32((acc[mi][nj][0] + bx) * sc),
                                        f2tf32((acc[mi][nj][1] + by) * sc));
                float2 v1 = make_float2(f2tf32((acc[mi][nj][2] + bx) * sc),
                                        f2tf32((acc[mi][nj][3] + by) * sc));
                *(float2*)&g_qkv[base + (((size_t)bb0 * NHEAD * SEQ) + nn0) * HDIM + dd] = v0;
                *(float2*)&g_qkv[base + (((size_t)bb1 * NHEAD * SEQ) + nn1) * HDIM + dd] = v1;
            } else {
                *(float2*)&Oout[(size_t)r0 * DIMC + col] =
                    make_float2(acc[mi][nj][0] + bx, acc[mi][nj][1] + by);
                *(float2*)&Oout[(size_t)(r0 + 8) * DIMC + col] =
                    make_float2(acc[mi][nj][2] + bx, acc[mi][nj][3] + by);
            }
        }
    }
}

// ---------------------------------------------------------------------------
// Flash attention v3: 128-key staging, SPLIT-HALF software pipeline.
// Per iteration instruction order keeps independent MMAs in flight during
// softmax ALU/MUFU: S-A, S-B | softmax-A | PV-A | softmax-B (indep of Oacc)
// | Oacc*aB (only op waiting on PV-A) | PV-B.
// ---------------------------------------------------------------------------
#define KSTR2 68
#define VSTR2 72
#define PSTR2 132
#define OFFK0 0
#define OFFK1 (128 * KSTR2)
#define OFFV0 (2 * 128 * KSTR2)
#define OFFV1 (OFFV0 + 128 * VSTR2)
#define OFFP  (OFFV0 + 2 * 128 * VSTR2)
#define ATTN_SMEM_BYTES ((OFFP + 128 * PSTR2) * 4)  // 210944

__global__ __launch_bounds__(256, 1)
void attn_mma_kernel()
{
    extern __shared__ float sm[];
    const uint32_t smb = smem_u32(sm);
    float* Ps = sm + OFFP;

    const int tid  = threadIdx.x;
    const int wid  = tid >> 5;
    const int lane = tid & 31;
    const int gq   = lane >> 2;
    const int gl   = lane & 3;
    const int q0   = blockIdx.x << 7;
    const int h    = blockIdx.y;
    const int b    = blockIdx.z;

    const size_t bh = ((size_t)b * NHEAD + h) * ((size_t)SEQ * HDIM);
    const float* Qg = g_qkv + bh + ((size_t)q0 << 6);
    const float* Kg = g_qkv + QKV_ONE + bh;
    const float* Vg = g_qkv + 2 * QKV_ONE + bh;

    // Stage Q -> Ps, load register fragments
#pragma unroll
    for (int p = 0; p < 8; p++) {
        const int idx = tid + (p << 8);
        const int row = idx >> 4;
        const int c4  = (idx & 15) << 2;
        *(float4*)&Ps[row * PSTR2 + c4] = *(const float4*)(Qg + ((size_t)row << 6) + c4);
    }
    __syncthreads();

    const int qr = (wid << 4) + gq;
    uint32_t aq[8][4];
#pragma unroll
    for (int ks = 0; ks < 8; ks++) {
        const int kc = (ks << 3) + gl;
        aq[ks][0] = __float_as_uint(Ps[qr * PSTR2 + kc]);
        aq[ks][1] = __float_as_uint(Ps[(qr + 8) * PSTR2 + kc]);
        aq[ks][2] = __float_as_uint(Ps[qr * PSTR2 + kc + 4]);
        aq[ks][3] = __float_as_uint(Ps[(qr + 8) * PSTR2 + kc + 4]);
    }
    __syncthreads();

    // Prologue staging: tile 0 -> buffer 0
    {
#pragma unroll
        for (int p = 0; p < 8; p++) {
            const int idx = tid + (p << 8);
            const int row = idx >> 4;
            const int c4  = (idx & 15) << 2;
            CP_ASYNC16(smb + (uint32_t)((OFFK0 + row * KSTR2 + c4) << 2),
                       Kg + ((size_t)row << 6) + c4);
            CP_ASYNC16(smb + (uint32_t)((OFFV0 + row * VSTR2 + c4) << 2),
                       Vg + ((size_t)row << 6) + c4);
        }
        CP_COMMIT();
    }

    float Oacc[8][4];
#pragma unroll
    for (int nj = 0; nj < 8; nj++)
#pragma unroll
        for (int r = 0; r < 4; r++) Oacc[nj][r] = 0.0f;
    float m0 = -1e30f, m1 = -1e30f, l0 = 0.0f, l1 = 0.0f;

    for (int kt = 0; kt < SEQ / 128; kt++) {
        CP_WAIT0();
        __syncthreads();

        if (kt + 1 < SEQ / 128) {
            const int koff = ((kt + 1) & 1) ? OFFK1 : OFFK0;
            const int voff = ((kt + 1) & 1) ? OFFV1 : OFFV0;
            const float* Kt = Kg + (((size_t)(kt + 1)) << 7) * HDIM;
            const float* Vt = Vg + (((size_t)(kt + 1)) << 7) * HDIM;
#pragma unroll
            for (int p = 0; p < 8; p++) {
                const int idx = tid + (p << 8);
                const int row = idx >> 4;
                const int c4  = (idx & 15) << 2;
                CP_ASYNC16(smb + (uint32_t)((koff + row * KSTR2 + c4) << 2),
                           Kt + ((size_t)row << 6) + c4);
                CP_ASYNC16(smb + (uint32_t)((voff + row * VSTR2 + c4) << 2),
                           Vt + ((size_t)row << 6) + c4);
            }
        }
        CP_COMMIT();

        const float* Ks = sm + ((kt & 1) ? OFFK1 : OFFK0);
        const float* Vs = sm + ((kt & 1) ? OFFV1 : OFFV0);

        // ---- S half A (keys 0..63) and half B (keys 64..127) ----
        float sA[8][4], sB[8][4];
#pragma unroll
        for (int nj = 0; nj < 8; nj++) {
            sA[nj][0] = sA[nj][1] = sA[nj][2] = sA[nj][3] = 0.0f;
            const int nrow = (nj << 3) + gq;
#pragma unroll
            for (int ks = 0; ks < 8; ks++) {
                const int kc = (ks << 3) + gl;
                mma_tf32(sA[nj], aq[ks],
                         __float_as_uint(Ks[nrow * KSTR2 + kc]),
                         __float_as_uint(Ks[nrow * KSTR2 + kc + 4]));
            }
        }
#pragma unroll
        for (int nj = 0; nj < 8; nj++) {
            sB[nj][0] = sB[nj][1] = sB[nj][2] = sB[nj][3] = 0.0f;
            const int nrow = 64 + (nj << 3) + gq;
#pragma unroll
            for (int ks = 0; ks < 8; ks++) {
                const int kc = (ks << 3) + gl;
                mma_tf32(sB[nj], aq[ks],
                         __float_as_uint(Ks[nrow * KSTR2 + kc]),
                         __float_as_uint(Ks[nrow * KSTR2 + kc + 4]));
            }
        }

        // ---- softmax A (S-B MMAs still in tensor pipe) ----
        {
            float c0 = -1e30f, c1 = -1e30f;
#pragma unroll
            for (int nj = 0; nj < 8; nj++) {
                c0 = fmaxf(c0, fmaxf(sA[nj][0], sA[nj][1]));
                c1 = fmaxf(c1, fmaxf(sA[nj][2], sA[nj][3]));
            }
            c0 = fmaxf(c0, __shfl_xor_sync(0xffffffffu, c0, 1));
            c0 = fmaxf(c0, __shfl_xor_sync(0xffffffffu, c0, 2));
            c1 = fmaxf(c1, __shfl_xor_sync(0xffffffffu, c1, 1));
            c1 = fmaxf(c1, __shfl_xor_sync(0xffffffffu, c1, 2));
            const float mn0 = fmaxf(m0, c0);
            const float mn1 = fmaxf(m1, c1);
            const float al0 = __expf(m0 - mn0);
            const float al1 = __expf(m1 - mn1);
            m0 = mn0; m1 = mn1;
            float r0 = 0.0f, r1 = 0.0f;
#pragma unroll
            for (int nj = 0; nj < 8; nj++) {
                sA[nj][0] = __expf(sA[nj][0] - mn0);
                sA[nj][1] = __expf(sA[nj][1] - mn0);
                sA[nj][2] = __expf(sA[nj][2] - mn1);
                sA[nj][3] = __expf(sA[nj][3] - mn1);
                r0 += sA[nj][0] + sA[nj][1];
                r1 += sA[nj][2] + sA[nj][3];
            }
            r0 += __shfl_xor_sync(0xffffffffu, r0, 1);
            r0 += __shfl_xor_sync(0xffffffffu, r0, 2);
            r1 += __shfl_xor_sync(0xffffffffu, r1, 1);
            r1 += __shfl_xor_sync(0xffffffffu, r1, 2);
            l0 = l0 * al0 + r0;
            l1 = l1 * al1 + r1;
#pragma unroll
            for (int nj = 0; nj < 8; nj++) {
                Oacc[nj][0] *= al0; Oacc[nj][1] *= al0;
                Oacc[nj][2] *= al1; Oacc[nj][3] *= al1;
            }
        }

        // ---- P-A store (cols 0..63) ----
#pragma unroll
        for (int nj = 0; nj < 8; nj++) {
            const int col = (nj << 3) + (gl << 1);
            *(float2*)&Ps[qr * PSTR2 + col] =
                make_float2(f2tf32(sA[nj][0]), f2tf32(sA[nj][1]));
            *(float2*)&Ps[(qr + 8) * PSTR2 + col] =
                make_float2(f2tf32(sA[nj][2]), f2tf32(sA[nj][3]));
        }
        __syncwarp();

        // ---- PV-A: keys 0..63 ----
#pragma unroll
        for (int ks = 0; ks < 8; ks++) {
            const int kc = (ks << 3) + gl;
            uint32_t pa[4];
            pa[0] = __float_as_uint(Ps[qr * PSTR2 + kc]);
            pa[1] = __float_as_uint(Ps[(qr + 8) * PSTR2 + kc]);
            pa[2] = __float_as_uint(Ps[qr * PSTR2 + kc + 4]);
            pa[3] = __float_as_uint(Ps[(qr + 8) * PSTR2 + kc + 4]);
#pragma unroll
            for (int nj = 0; nj < 8; nj++) {
                const int d = (nj << 3) + gq;
                mma_tf32(Oacc[nj], pa,
                         __float_as_uint(Vs[kc * VSTR2 + d]),
                         __float_as_uint(Vs[(kc + 4) * VSTR2 + d]));
            }
        }

        // ---- softmax B stats/exp/P-store (independent of Oacc; overlaps PV-A) ----
        float alB0, alB1;
        {
            float c0 = -1e30f, c1 = -1e30f;
#pragma unroll
            for (int nj = 0; nj < 8; nj++) {
                c0 = fmaxf(c0, fmaxf(sB[nj][0], sB[nj][1]));
                c1 = fmaxf(c1, fmaxf(sB[nj][2], sB[nj][3]));
            }
            c0 = fmaxf(c0, __shfl_xor_sync(0xffffffffu, c0, 1));
            c0 = fmaxf(c0, __shfl_xor_sync(0xffffffffu, c0, 2));
            c1 = fmaxf(c1, __shfl_xor_sync(0xffffffffu, c1, 1));
            c1 = fmaxf(c1, __shfl_xor_sync(0xffffffffu, c1, 2));
            const float mn0 = fmaxf(m0, c0);
            const float mn1 = fmaxf(m1, c1);
            alB0 = __expf(m0 - mn0);
            alB1 = __expf(m1 - mn1);
            m0 = mn0; m1 = mn1;
            float r0 = 0.0f, r1 = 0.0f;
#pragma unroll
            for (int nj = 0; nj < 8; nj++) {
                sB[nj][0] = __expf(sB[nj][0] - mn0);
                sB[nj][1] = __expf(sB[nj][1] - mn0);
                sB[nj][2] = __expf(sB[nj][2] - mn1);
                sB[nj][3] = __expf(sB[nj][3] - mn1);
                r0 += sB[nj][0] + sB[nj][1];
                r1 += sB[nj][2] + sB[nj][3];
            }
            r0 += __shfl_xor_sync(0xffffffffu, r0, 1);
            r0 += __shfl_xor_sync(0xffffffffu, r0, 2);
            r1 += __shfl_xor_sync(0xffffffffu, r1, 1);
            r1 += __shfl_xor_sync(0xffffffffu, r1, 2);
            l0 = l0 * alB0 + r0;
            l1 = l1 * alB1 + r1;
        }
#pragma unroll
        for (int nj = 0; nj < 8; nj++) {
            const int col = 64 + (nj << 3) + (gl << 1);
            *(float2*)&Ps[qr * PSTR2 + col] =
                make_float2(f2tf32(sB[nj][0]), f2tf32(sB[nj][1]));
            *(float2*)&Ps[(qr + 8) * PSTR2 + col] =
                make_float2(f2tf32(sB[nj][2]), f2tf32(sB[nj][3]));
        }
        __syncwarp();

        // ---- Oacc rescale for B (first op that waits on PV-A results) ----
#pragma unroll
        for (int nj = 0; nj < 8; nj++) {
            Oacc[nj][0] *= alB0; Oacc[nj][1] *= alB0;
            Oacc[nj][2] *= alB1; Oacc[nj][3] *= alB1;
        }

        // ---- PV-B: keys 64..127 ----
#pragma unroll
        for (int ks = 0; ks < 8; ks++) {
            const int kc = 64 + (ks << 3) + gl;
            uint32_t pa[4];
            pa[0] = __float_as_uint(Ps[qr * PSTR2 + kc]);
            pa[1] = __float_as_uint(Ps[(qr + 8) * PSTR2 + kc]);
            pa[2] = __float_as_uint(Ps[qr * PSTR2 + kc + 4]);
            pa[3] = __float_as_uint(Ps[(qr + 8) * PSTR2 + kc + 4]);
#pragma unroll
            for (int nj = 0; nj < 8; nj++) {
                const int d = (nj << 3) + gq;
                mma_tf32(Oacc[nj], pa,
                         __float_as_uint(Vs[kc * VSTR2 + d]),
                         __float_as_uint(Vs[(kc + 4) * VSTR2 + d]));
            }
        }
    }

    const float inv0 = 1.0f / l0;
    const float inv1 = 1.0f / l1;
    const int n0 = q0 + qr;
    float* dst0 = &g_attn[((size_t)b * SEQ + n0) * DIMC + h * HDIM];
    float* dst1 = &g_attn[((size_t)b * SEQ + n0 + 8) * DIMC + h * HDIM];
#pragma unroll
    for (int nj = 0; nj < 8; nj++) {
        const int col = (nj << 3) + (gl << 1);
        *(float2*)(dst0 + col) = make_float2(f2tf32(Oacc[nj][0] * inv0),
                                             f2tf32(Oacc[nj][1] * inv0));
        *(float2*)(dst1 + col) = make_float2(f2tf32(Oacc[nj][2] * inv1),
                                             f2tf32(Oacc[nj][3] * inv1));
    }
}

// ---------------------------------------------------------------------------
extern "C" void kernel_launch(void* const* d_in, const int* in_sizes, int n_in,
                              void* d_out, int out_size)
{
    (void)in_sizes; (void)n_in; (void)out_size;
    const float* x      = (const float*)d_in[0];
    const float* w_qkv  = (const float*)d_in[1];
    const float* b_qkv  = (const float*)d_in[2];
    const float* w_proj = (const float*)d_in[3];
    const float* b_proj = (const float*)d_in[4];
    float* out = (float*)d_out;

    cudaFuncSetAttribute(mma_gemm<0>, cudaFuncAttributeMaxDynamicSharedMemorySize, GEMM_SMEM_BYTES);
    cudaFuncSetAttribute(mma_gemm<1>, cudaFuncAttributeMaxDynamicSharedMemorySize, GEMM_SMEM_BYTES);
    cudaFuncSetAttribute(attn_mma_kernel, cudaFuncAttributeMaxDynamicSharedMemorySize, ATTN_SMEM_BYTES);

    // 0) Pre-round inputs to tf32 (rna)
    round_tf32_kernel<<<1024, 256>>>((const float4*)x,      0, (int)((size_t)MROWS * DIMC / 4));
    round_tf32_kernel<<<2048, 256>>>((const float4*)w_qkv,  1, (int)((size_t)DIMC * 3 * DIMC / 4));
    round_tf32_kernel<<<1024, 256>>>((const float4*)w_proj, 2, (int)((size_t)DIMC * DIMC / 4));

    // 1) QKV GEMM -> g_qkv (rounded, Q pre-scaled)
    {
        dim3 grid(MROWS / 128, 3 * DIMC / 128);
        mma_gemm<0><<<grid, 256, GEMM_SMEM_BYTES>>>(b_qkv, nullptr);
    }
    // 2) Attention -> g_attn (rounded)
    {
        dim3 grid(SEQ / 128, NHEAD, BATCH);
        attn_mma_kernel<<<grid, 256, ATTN_SMEM_BYTES>>>();
    }
    // 3) Projection -> d_out (fp32)
    {
        dim3 grid(MROWS / 128, DIMC / 128);
        mma_gemm<1><<<grid, 256, GEMM_SMEM_BYTES>>>(b_proj, out);
    }
}

// round 15
// speedup vs baseline: 1.6839x; 1.0335x over previous
#include <cuda_runtime.h>
#include <cstdint>
#include <math.h>

#define DIMC    2560
#define NHEAD   40
#define HDIM    64
#define BATCH   2
#define SEQ     2048
#define MROWS   (BATCH * SEQ)
#define QKV_ONE ((size_t)BATCH * NHEAD * SEQ * HDIM)
#define ATTN_SCALE 0.125f

// Scratch (__device__ globals; allocation-free rule)
__device__ __align__(16) float g_qkv[3u * BATCH * NHEAD * SEQ * HDIM]; // tf32-rounded, Q pre-scaled
__device__ __align__(16) float g_attn[(size_t)MROWS * DIMC];           // tf32-rounded
__device__ __align__(16) float g_x[(size_t)MROWS * DIMC];
__device__ __align__(16) float g_wqkv[(size_t)DIMC * 3 * DIMC];
__device__ __align__(16) float g_wproj[(size_t)DIMC * DIMC];

// ---------------------------------------------------------------------------
__device__ __forceinline__ float f2tf32(float x) {
    uint32_t u;
    asm("cvt.rna.tf32.f32 %0, %1;" : "=r"(u) : "f"(x));
    return __uint_as_float(u);
}
__device__ __forceinline__ void mma_tf32(float* c, const uint32_t* a,
                                         uint32_t b0, uint32_t b1) {
    asm volatile(
        "mma.sync.aligned.m16n8k8.row.col.f32.tf32.tf32.f32 "
        "{%0,%1,%2,%3}, {%4,%5,%6,%7}, {%8,%9}, {%0,%1,%2,%3};"
        : "+f"(c[0]), "+f"(c[1]), "+f"(c[2]), "+f"(c[3])
        : "r"(a[0]), "r"(a[1]), "r"(a[2]), "r"(a[3]), "r"(b0), "r"(b1));
}
__device__ __forceinline__ uint32_t smem_u32(const void* p) {
    uint32_t a;
    asm("{ .reg .u64 t; cvta.to.shared.u64 t, %1; cvt.u32.u64 %0, t; }" : "=r"(a) : "l"(p));
    return a;
}
#define CP_ASYNC16(dst, src) \
    asm volatile("cp.async.cg.shared.global [%0], [%1], 16;" :: "r"(dst), "l"(src) : "memory")
#define CP_COMMIT() asm volatile("cp.async.commit_group;" ::: "memory")
#define CP_WAIT1()  asm volatile("cp.async.wait_group 1;" ::: "memory")
#define CP_WAIT0()  asm volatile("cp.async.wait_group 0;" ::: "memory")

// ---------------------------------------------------------------------------
// Pre-pass (merged): tf32-round x / w_qkv / w_proj in one launch.
// ---------------------------------------------------------------------------
#define N4_X   ((int)((size_t)MROWS * DIMC / 4))
#define N4_WQ  ((int)((size_t)DIMC * 3 * DIMC / 4))
#define N4_WP  ((int)((size_t)DIMC * DIMC / 4))

__global__ void round_tf32_all(const float4* __restrict__ x,
                               const float4* __restrict__ wq,
                               const float4* __restrict__ wp)
{
    const int total = N4_X + N4_WQ + N4_WP;
    const int stride = gridDim.x * blockDim.x;
    for (int i = blockIdx.x * blockDim.x + threadIdx.x; i < total; i += stride) {
        const float4* src;
        float4* dst;
        int j = i;
        if (j < N4_X)            { src = x;  dst = (float4*)g_x; }
        else if ((j -= N4_X) < N4_WQ) { src = wq; dst = (float4*)g_wqkv; }
        else                     { j -= N4_WQ; src = wp; dst = (float4*)g_wproj; }
        float4 v = src[j];
        v.x = f2tf32(v.x); v.y = f2tf32(v.y);
        v.z = f2tf32(v.z); v.w = f2tf32(v.w);
        dst[j] = v;
    }
}

// ---------------------------------------------------------------------------
// TF32 GEMM (FROZEN from R12: at mma.sync issue ceiling, 198 TF/s)
// CTA 128x128, BK=32, 3-stage cp.async, 2 CTAs/SM, warp tile 64x32.
// ---------------------------------------------------------------------------
#define G_STAGE_FL 8192
#define GEMM_SMEM_BYTES (3 * G_STAGE_FL * 4)   // 98304

template <int MODE>
__global__ __launch_bounds__(256, 2)
void mma_gemm(const float* __restrict__ bias, float* __restrict__ Oout)
{
    extern __shared__ float sm[];
    const uint32_t smb = smem_u32(sm);
    const int tid  = threadIdx.x;
    const int wid  = tid >> 5;
    const int lane = tid & 31;
    const int q    = lane >> 2;
    const int lp   = lane & 3;
    const int wm   = wid & 1;
    const int wn   = wid >> 1;
    const int bm   = blockIdx.x << 7;
    const int bn   = blockIdx.y << 7;
    const int K    = DIMC;
    const int nch  = K / 32;
    const int Nout = (MODE == 0) ? 3 * DIMC : DIMC;

    const float* Ag = (MODE == 0) ? g_x : g_attn;
    const float* W  = (MODE == 0) ? g_wqkv : g_wproj;

    const int lm  = tid >> 3;
    const int lc4 = (tid & 7) << 2;
    const uint32_t a_sw = (uint32_t)(lc4 ^ ((lm & 7) << 2));
    const int lk0 = tid >> 5;
    const int ln  = (tid & 31) << 2;
    const uint32_t b_sw = (uint32_t)(ln ^ ((lk0 & 3) << 3));

    const float* Abase = Ag + (size_t)(bm + lm) * K + lc4;
    const float* Wbase = W + (size_t)lk0 * Nout + bn + ln;

    float acc[4][4][4];
#pragma unroll
    for (int mi = 0; mi < 4; mi++)
#pragma unroll
        for (int nj = 0; nj < 4; nj++)
#pragma unroll
            for (int r = 0; r < 4; r++) acc[mi][nj][r] = 0.0f;

#pragma unroll
    for (int s = 0; s < 2; s++) {
        const uint32_t sb = smb + (uint32_t)s * (G_STAGE_FL * 4);
        const int kc = s << 5;
#pragma unroll
        for (int p = 0; p < 4; p++)
            CP_ASYNC16(sb + ((((uint32_t)(lm + (p << 5))) << 5) + a_sw) * 4u,
                       Abase + kc + (size_t)(p << 5) * K);
#pragma unroll
        for (int p = 0; p < 4; p++)
            CP_ASYNC16(sb + 16384u + ((((uint32_t)(lk0 + (p << 3))) << 7) + b_sw) * 4u,
                       Wbase + (size_t)(kc + (p << 3)) * Nout);
        CP_COMMIT();
    }

    for (int c = 0; c < nch; c++) {
        CP_WAIT1();
        __syncthreads();
        if (c + 2 < nch) {
            const uint32_t sb = smb + (uint32_t)((c + 2) % 3) * (G_STAGE_FL * 4);
            const int kc = (c + 2) << 5;
#pragma unroll
            for (int p = 0; p < 4; p++)
                CP_ASYNC16(sb + ((((uint32_t)(lm + (p << 5))) << 5) + a_sw) * 4u,
                           Abase + kc + (size_t)(p << 5) * K);
#pragma unroll
            for (int p = 0; p < 4; p++)
                CP_ASYNC16(sb + 16384u + ((((uint32_t)(lk0 + (p << 3))) << 7) + b_sw) * 4u,
                           Wbase + (size_t)(kc + (p << 3)) * Nout);
        }
        CP_COMMIT();

        const float* As = sm + (c % 3) * G_STAGE_FL;
        const float* Bs = As + 4096;
#pragma unroll
        for (int ks = 0; ks < 4; ks++) {
            const int kcol = (ks << 3) + lp;
            const int off0 = kcol ^ (q << 2);
            const int off4 = off0 ^ 4;
            uint32_t a[4][4];
#pragma unroll
            for (int mi = 0; mi < 4; mi++) {
                const float* ap = As + (((wm << 6) + (mi << 4) + q) << 5);
                a[mi][0] = __float_as_uint(ap[off0]);
                a[mi][1] = __float_as_uint(ap[256 + off0]);
                a[mi][2] = __float_as_uint(ap[off4]);
                a[mi][3] = __float_as_uint(ap[256 + off4]);
            }
#pragma unroll
            for (int nj = 0; nj < 4; nj++) {
                const float* bp = Bs + (kcol << 7)
                                     + (wn << 5) + ((nj ^ lp) << 3) + q;
                const uint32_t b0 = __float_as_uint(bp[0]);
                const uint32_t b1 = __float_as_uint(bp[512]);
#pragma unroll
                for (int mi = 0; mi < 4; mi++)
                    mma_tf32(acc[mi][nj], a[mi], b0, b1);
            }
        }
    }

#pragma unroll
    for (int mi = 0; mi < 4; mi++) {
        const int r0 = bm + (wm << 6) + (mi << 4) + q;
#pragma unroll
        for (int nj = 0; nj < 4; nj++) {
            const int col = bn + (wn << 5) + (nj << 3) + (lp << 1);
            const float bx = bias[col];
            const float by = bias[col + 1];
            if (MODE == 0) {
                const int which = col / DIMC;
                const int cc = col - which * DIMC;
                const int hh = cc >> 6;
                const int dd = cc & 63;
                const float sc = (which == 0) ? ATTN_SCALE : 1.0f;
                const int bb0 = r0 >> 11, nn0 = r0 & 2047;
                const int r1 = r0 + 8;
                const int bb1 = r1 >> 11, nn1 = r1 & 2047;
                const size_t base = (((size_t)which * BATCH) * NHEAD + hh) * SEQ * HDIM;
                float2 v0 = make_float2(f2tf32((acc[mi][nj][0] + bx) * sc),
                                        f2tf32((acc[mi][nj][1] + by) * sc));
                float2 v1 = make_float2(f2tf32((acc[mi][nj][2] + bx) * sc),
                                        f2tf32((acc[mi][nj][3] + by) * sc));
                *(float2*)&g_qkv[base + (((size_t)bb0 * NHEAD * SEQ) + nn0) * HDIM + dd] = v0;
                *(float2*)&g_qkv[base + (((size_t)bb1 * NHEAD * SEQ) + nn1) * HDIM + dd] = v1;
            } else {
                *(float2*)&Oout[(size_t)r0 * DIMC + col] =
                    make_float2(acc[mi][nj][0] + bx, acc[mi][nj][1] + by);
                *(float2*)&Oout[(size_t)(r0 + 8) * DIMC + col] =
                    make_float2(acc[mi][nj][2] + bx, acc[mi][nj][3] + by);
            }
        }
    }
}

// ---------------------------------------------------------------------------
// Flash attention v4: 64-key tiles, cp.async double-buffered, 104 KB smem
// -> 2 CTAs/SM. One __syncthreads per iteration. 8 warps x 16 q-rows.
// ---------------------------------------------------------------------------
#define KSTR 68
#define VSTR 72
#define PSTR 68
#define OFFK0 0
#define OFFK1 (64 * KSTR)                 // 4352
#define OFFV0 (2 * 64 * KSTR)             // 8704
#define OFFV1 (OFFV0 + 64 * VSTR)         // 13312
#define OFFP  (OFFV0 + 2 * 64 * VSTR)     // 17920
#define ATTN_SMEM_BYTES ((OFFP + 128 * PSTR) * 4)   // 106496

__global__ __launch_bounds__(256, 2)
void attn_mma_kernel()
{
    extern __shared__ float sm[];
    const uint32_t smb = smem_u32(sm);
    float* Ps = sm + OFFP;

    const int tid  = threadIdx.x;
    const int wid  = tid >> 5;
    const int lane = tid & 31;
    const int gq   = lane >> 2;
    const int gl   = lane & 3;
    const int q0   = blockIdx.x << 7;
    const int h    = blockIdx.y;
    const int b    = blockIdx.z;

    const size_t bh = ((size_t)b * NHEAD + h) * ((size_t)SEQ * HDIM);
    const float* Qg = g_qkv + bh + ((size_t)q0 << 6);
    const float* Kg = g_qkv + QKV_ONE + bh;
    const float* Vg = g_qkv + 2 * QKV_ONE + bh;

    // Stage Q (pre-rounded, pre-scaled) -> Ps, then register fragments
#pragma unroll
    for (int p = 0; p < 8; p++) {
        const int idx = tid + (p << 8);
        const int row = idx >> 4;
        const int c4  = (idx & 15) << 2;
        *(float4*)&Ps[row * PSTR + c4] = *(const float4*)(Qg + ((size_t)row << 6) + c4);
    }
    __syncthreads();

    const int qr = (wid << 4) + gq;
    uint32_t aq[8][4];
#pragma unroll
    for (int ks = 0; ks < 8; ks++) {
        const int kc = (ks << 3) + gl;
        aq[ks][0] = __float_as_uint(Ps[qr * PSTR + kc]);
        aq[ks][1] = __float_as_uint(Ps[(qr + 8) * PSTR + kc]);
        aq[ks][2] = __float_as_uint(Ps[qr * PSTR + kc + 4]);
        aq[ks][3] = __float_as_uint(Ps[(qr + 8) * PSTR + kc + 4]);
    }
    __syncthreads();   // Ps now free for P tiles

    // Prologue: stage K/V tile 0 -> buffer 0 (64x64 each; 4 float4/thread)
    {
#pragma unroll
        for (int p = 0; p < 4; p++) {
            const int idx = tid + (p << 8);
            const int row = idx >> 4;     // 0..63
            const int c4  = (idx & 15) << 2;
            CP_ASYNC16(smb + (uint32_t)((OFFK0 + row * KSTR + c4) << 2),
                       Kg + ((size_t)row << 6) + c4);
            CP_ASYNC16(smb + (uint32_t)((OFFV0 + row * VSTR + c4) << 2),
                       Vg + ((size_t)row << 6) + c4);
        }
        CP_COMMIT();
    }

    float Oacc[8][4];
#pragma unroll
    for (int nj = 0; nj < 8; nj++)
#pragma unroll
        for (int r = 0; r < 4; r++) Oacc[nj][r] = 0.0f;
    float m0 = -1e30f, m1 = -1e30f, l0 = 0.0f, l1 = 0.0f;

    for (int kt = 0; kt < SEQ / 64; kt++) {
        CP_WAIT0();
        __syncthreads();   // tile kt visible; all warps done with tile kt-1

        if (kt + 1 < SEQ / 64) {
            const int koff = ((kt + 1) & 1) ? OFFK1 : OFFK0;
            const int voff = ((kt + 1) & 1) ? OFFV1 : OFFV0;
            const float* Kt = Kg + (((size_t)(kt + 1)) << 6) * HDIM;
            const float* Vt = Vg + (((size_t)(kt + 1)) << 6) * HDIM;
#pragma unroll
            for (int p = 0; p < 4; p++) {
                const int idx = tid + (p << 8);
                const int row = idx >> 4;
                const int c4  = (idx & 15) << 2;
                CP_ASYNC16(smb + (uint32_t)((koff + row * KSTR + c4) << 2),
                           Kt + ((size_t)row << 6) + c4);
                CP_ASYNC16(smb + (uint32_t)((voff + row * VSTR + c4) << 2),
                           Vt + ((size_t)row << 6) + c4);
            }
        }
        CP_COMMIT();

        const float* Ks = sm + ((kt & 1) ? OFFK1 : OFFK0);
        const float* Vs = sm + ((kt & 1) ? OFFV1 : OFFV0);

        // ---- S = Q K^T : 8 n-tiles (64 keys) x 8 k-steps ----
        float s[8][4];
#pragma unroll
        for (int nj = 0; nj < 8; nj++) {
            s[nj][0] = 0.0f; s[nj][1] = 0.0f; s[nj][2] = 0.0f; s[nj][3] = 0.0f;
            const int nrow = (nj << 3) + gq;
#pragma unroll
            for (int ks = 0; ks < 8; ks++) {
                const int kc = (ks << 3) + gl;
                mma_tf32(s[nj], aq[ks],
                         __float_as_uint(Ks[nrow * KSTR + kc]),
                         __float_as_uint(Ks[nrow * KSTR + kc + 4]));
            }
        }

        // ---- Online softmax (quad reduce over lane bits 0,1) ----
        float c0 = -1e30f, c1 = -1e30f;
#pragma unroll
        for (int nj = 0; nj < 8; nj++) {
            c0 = fmaxf(c0, fmaxf(s[nj][0], s[nj][1]));
            c1 = fmaxf(c1, fmaxf(s[nj][2], s[nj][3]));
        }
        c0 = fmaxf(c0, __shfl_xor_sync(0xffffffffu, c0, 1));
        c0 = fmaxf(c0, __shfl_xor_sync(0xffffffffu, c0, 2));
        c1 = fmaxf(c1, __shfl_xor_sync(0xffffffffu, c1, 1));
        c1 = fmaxf(c1, __shfl_xor_sync(0xffffffffu, c1, 2));
        const float mn0 = fmaxf(m0, c0);
        const float mn1 = fmaxf(m1, c1);
        const float al0 = __expf(m0 - mn0);
        const float al1 = __expf(m1 - mn1);
        m0 = mn0; m1 = mn1;

        float r0 = 0.0f, r1 = 0.0f;
#pragma unroll
        for (int nj = 0; nj < 8; nj++) {
            s[nj][0] = __expf(s[nj][0] - mn0);
            s[nj][1] = __expf(s[nj][1] - mn0);
            s[nj][2] = __expf(s[nj][2] - mn1);
            s[nj][3] = __expf(s[nj][3] - mn1);
            r0 += s[nj][0] + s[nj][1];
            r1 += s[nj][2] + s[nj][3];
        }
        r0 += __shfl_xor_sync(0xffffffffu, r0, 1);
        r0 += __shfl_xor_sync(0xffffffffu, r0, 2);
        r1 += __shfl_xor_sync(0xffffffffu, r1, 1);
        r1 += __shfl_xor_sync(0xffffffffu, r1, 2);
        l0 = l0 * al0 + r0;
        l1 = l1 * al1 + r1;
#pragma unroll
        for (int nj = 0; nj < 8; nj++) {
            Oacc[nj][0] *= al0; Oacc[nj][1] *= al0;
            Oacc[nj][2] *= al1; Oacc[nj][3] *= al1;
        }

        // ---- P -> per-warp-private smem rows (qr, qr+8), tf32-rounded ----
#pragma unroll
        for (int nj = 0; nj < 8; nj++) {
            const int col = (nj << 3) + (gl << 1);
            *(float2*)&Ps[qr * PSTR + col] =
                make_float2(f2tf32(s[nj][0]), f2tf32(s[nj][1]));
            *(float2*)&Ps[(qr + 8) * PSTR + col] =
                make_float2(f2tf32(s[nj][2]), f2tf32(s[nj][3]));
        }
        __syncwarp();

        // ---- O += P V : 8 k-steps (64 keys) x 8 d-tiles ----
#pragma unroll
        for (int ks = 0; ks < 8; ks++) {
            const int kc = (ks << 3) + gl;
            uint32_t pa[4];
            pa[0] = __float_as_uint(Ps[qr * PSTR + kc]);
            pa[1] = __float_as_uint(Ps[(qr + 8) * PSTR + kc]);
            pa[2] = __float_as_uint(Ps[qr * PSTR + kc + 4]);
            pa[3] = __float_as_uint(Ps[(qr + 8) * PSTR + kc + 4]);
#pragma unroll
            for (int nj = 0; nj < 8; nj++) {
                const int d = (nj << 3) + gq;
                mma_tf32(Oacc[nj], pa,
                         __float_as_uint(Vs[kc * VSTR + d]),
                         __float_as_uint(Vs[(kc + 4) * VSTR + d]));
            }
        }
    }

    // ---- Epilogue: normalize + tf32-round into g_attn ----
    const float inv0 = 1.0f / l0;
    const float inv1 = 1.0f / l1;
    const int n0 = q0 + qr;
    float* dst0 = &g_attn[((size_t)b * SEQ + n0) * DIMC + h * HDIM];
    float* dst1 = &g_attn[((size_t)b * SEQ + n0 + 8) * DIMC + h * HDIM];
#pragma unroll
    for (int nj = 0; nj < 8; nj++) {
        const int col = (nj << 3) + (gl << 1);
        *(float2*)(dst0 + col) = make_float2(f2tf32(Oacc[nj][0] * inv0),
                                             f2tf32(Oacc[nj][1] * inv0));
        *(float2*)(dst1 + col) = make_float2(f2tf32(Oacc[nj][2] * inv1),
                                             f2tf32(Oacc[nj][3] * inv1));
    }
}

// ---------------------------------------------------------------------------
extern "C" void kernel_launch(void* const* d_in, const int* in_sizes, int n_in,
                              void* d_out, int out_size)
{
    (void)in_sizes; (void)n_in; (void)out_size;
    const float* x      = (const float*)d_in[0];
    const float* w_qkv  = (const float*)d_in[1];
    const float* b_qkv  = (const float*)d_in[2];
    const float* w_proj = (const float*)d_in[3];
    const float* b_proj = (const float*)d_in[4];
    float* out = (float*)d_out;

    cudaFuncSetAttribute(mma_gemm<0>, cudaFuncAttributeMaxDynamicSharedMemorySize, GEMM_SMEM_BYTES);
    cudaFuncSetAttribute(mma_gemm<1>, cudaFuncAttributeMaxDynamicSharedMemorySize, GEMM_SMEM_BYTES);
    cudaFuncSetAttribute(attn_mma_kernel, cudaFuncAttributeMaxDynamicSharedMemorySize, ATTN_SMEM_BYTES);

    // 0) Pre-round inputs to tf32 (single merged launch)
    round_tf32_all<<<2048, 256>>>((const float4*)x, (const float4*)w_qkv,
                                  (const float4*)w_proj);

    // 1) QKV GEMM -> g_qkv (rounded, Q pre-scaled)
    {
        dim3 grid(MROWS / 128, 3 * DIMC / 128);
        mma_gemm<0><<<grid, 256, GEMM_SMEM_BYTES>>>(b_qkv, nullptr);
    }
    // 2) Attention -> g_attn (rounded); 2 CTAs/SM
    {
        dim3 grid(SEQ / 128, NHEAD, BATCH);
        attn_mma_kernel<<<grid, 256, ATTN_SMEM_BYTES>>>();
    }
    // 3) Projection -> d_out (fp32)
    {
        dim3 grid(MROWS / 128, DIMC / 128);
        mma_gemm<1><<<grid, 256, GEMM_SMEM_BYTES>>>(b_proj, out);
    }
}

// round 17
// speedup vs baseline: 1.6980x; 1.0084x over previous
#include <cuda_runtime.h>
#include <cstdint>
#include <math.h>

#define DIMC    2560
#define NHEAD   40
#define HDIM    64
#define BATCH   2
#define SEQ     2048
#define MROWS   (BATCH * SEQ)
#define QKV_ONE ((size_t)BATCH * NHEAD * SEQ * HDIM)
// Q pre-scale now folds log2(e): scores come out of the S-MMA in exp2 domain.
#define Q_SCALE 0.18033688011112042f   // 0.125 * log2(e)

// Scratch (__device__ globals; allocation-free rule)
__device__ __align__(16) float g_qkv[3u * BATCH * NHEAD * SEQ * HDIM]; // tf32-rounded, Q pre-scaled by Q_SCALE
__device__ __align__(16) float g_attn[(size_t)MROWS * DIMC];           // tf32-rounded
__device__ __align__(16) float g_x[(size_t)MROWS * DIMC];
__device__ __align__(16) float g_wqkv[(size_t)DIMC * 3 * DIMC];
__device__ __align__(16) float g_wproj[(size_t)DIMC * DIMC];

// ---------------------------------------------------------------------------
__device__ __forceinline__ float f2tf32(float x) {
    uint32_t u;
    asm("cvt.rna.tf32.f32 %0, %1;" : "=r"(u) : "f"(x));
    return __uint_as_float(u);
}
__device__ __forceinline__ void mma_tf32(float* c, const uint32_t* a,
                                         uint32_t b0, uint32_t b1) {
    asm volatile(
        "mma.sync.aligned.m16n8k8.row.col.f32.tf32.tf32.f32 "
        "{%0,%1,%2,%3}, {%4,%5,%6,%7}, {%8,%9}, {%0,%1,%2,%3};"
        : "+f"(c[0]), "+f"(c[1]), "+f"(c[2]), "+f"(c[3])
        : "r"(a[0]), "r"(a[1]), "r"(a[2]), "r"(a[3]), "r"(b0), "r"(b1));
}
__device__ __forceinline__ uint32_t smem_u32(const void* p) {
    uint32_t a;
    asm("{ .reg .u64 t; cvta.to.shared.u64 t, %1; cvt.u32.u64 %0, t; }" : "=r"(a) : "l"(p));
    return a;
}
#define CP_ASYNC16(dst, src) \
    asm volatile("cp.async.cg.shared.global [%0], [%1], 16;" :: "r"(dst), "l"(src) : "memory")
#define CP_COMMIT() asm volatile("cp.async.commit_group;" ::: "memory")
#define CP_WAIT1()  asm volatile("cp.async.wait_group 1;" ::: "memory")
#define CP_WAIT0()  asm volatile("cp.async.wait_group 0;" ::: "memory")

// ---------------------------------------------------------------------------
// Pre-pass (merged): tf32-round x / w_qkv / w_proj in one launch.
// ---------------------------------------------------------------------------
#define N4_X   ((int)((size_t)MROWS * DIMC / 4))
#define N4_WQ  ((int)((size_t)DIMC * 3 * DIMC / 4))
#define N4_WP  ((int)((size_t)DIMC * DIMC / 4))

__global__ void round_tf32_all(const float4* __restrict__ x,
                               const float4* __restrict__ wq,
                               const float4* __restrict__ wp)
{
    const int total = N4_X + N4_WQ + N4_WP;
    const int stride = gridDim.x * blockDim.x;
    for (int i = blockIdx.x * blockDim.x + threadIdx.x; i < total; i += stride) {
        const float4* src;
        float4* dst;
        int j = i;
        if (j < N4_X)            { src = x;  dst = (float4*)g_x; }
        else if ((j -= N4_X) < N4_WQ) { src = wq; dst = (float4*)g_wqkv; }
        else                     { j -= N4_WQ; src = wp; dst = (float4*)g_wproj; }
        float4 v = src[j];
        v.x = f2tf32(v.x); v.y = f2tf32(v.y);
        v.z = f2tf32(v.z); v.w = f2tf32(v.w);
        dst[j] = v;
    }
}

// ---------------------------------------------------------------------------
// TF32 GEMM (FROZEN from R12/R14: at mma.sync issue ceiling, 198 TF/s)
// CTA 128x128, BK=32, 3-stage cp.async, 2 CTAs/SM, warp tile 64x32.
// ---------------------------------------------------------------------------
#define G_STAGE_FL 8192
#define GEMM_SMEM_BYTES (3 * G_STAGE_FL * 4)   // 98304

template <int MODE>
__global__ __launch_bounds__(256, 2)
void mma_gemm(const float* __restrict__ bias, float* __restrict__ Oout)
{
    extern __shared__ float sm[];
    const uint32_t smb = smem_u32(sm);
    const int tid  = threadIdx.x;
    const int wid  = tid >> 5;
    const int lane = tid & 31;
    const int q    = lane >> 2;
    const int lp   = lane & 3;
    const int wm   = wid & 1;
    const int wn   = wid >> 1;
    const int bm   = blockIdx.x << 7;
    const int bn   = blockIdx.y << 7;
    const int K    = DIMC;
    const int nch  = K / 32;
    const int Nout = (MODE == 0) ? 3 * DIMC : DIMC;

    const float* Ag = (MODE == 0) ? g_x : g_attn;
    const float* W  = (MODE == 0) ? g_wqkv : g_wproj;

    const int lm  = tid >> 3;
    const int lc4 = (tid & 7) << 2;
    const uint32_t a_sw = (uint32_t)(lc4 ^ ((lm & 7) << 2));
    const int lk0 = tid >> 5;
    const int ln  = (tid & 31) << 2;
    const uint32_t b_sw = (uint32_t)(ln ^ ((lk0 & 3) << 3));

    const float* Abase = Ag + (size_t)(bm + lm) * K + lc4;
    const float* Wbase = W + (size_t)lk0 * Nout + bn + ln;

    float acc[4][4][4];
#pragma unroll
    for (int mi = 0; mi < 4; mi++)
#pragma unroll
        for (int nj = 0; nj < 4; nj++)
#pragma unroll
            for (int r = 0; r < 4; r++) acc[mi][nj][r] = 0.0f;

#pragma unroll
    for (int s = 0; s < 2; s++) {
        const uint32_t sb = smb + (uint32_t)s * (G_STAGE_FL * 4);
        const int kc = s << 5;
#pragma unroll
        for (int p = 0; p < 4; p++)
            CP_ASYNC16(sb + ((((uint32_t)(lm + (p << 5))) << 5) + a_sw) * 4u,
                       Abase + kc + (size_t)(p << 5) * K);
#pragma unroll
        for (int p = 0; p < 4; p++)
            CP_ASYNC16(sb + 16384u + ((((uint32_t)(lk0 + (p << 3))) << 7) + b_sw) * 4u,
                       Wbase + (size_t)(kc + (p << 3)) * Nout);
        CP_COMMIT();
    }

    for (int c = 0; c < nch; c++) {
        CP_WAIT1();
        __syncthreads();
        if (c + 2 < nch) {
            const uint32_t sb = smb + (uint32_t)((c + 2) % 3) * (G_STAGE_FL * 4);
            const int kc = (c + 2) << 5;
#pragma unroll
            for (int p = 0; p < 4; p++)
                CP_ASYNC16(sb + ((((uint32_t)(lm + (p << 5))) << 5) + a_sw) * 4u,
                           Abase + kc + (size_t)(p << 5) * K);
#pragma unroll
            for (int p = 0; p < 4; p++)
                CP_ASYNC16(sb + 16384u + ((((uint32_t)(lk0 + (p << 3))) << 7) + b_sw) * 4u,
                           Wbase + (size_t)(kc + (p << 3)) * Nout);
        }
        CP_COMMIT();

        const float* As = sm + (c % 3) * G_STAGE_FL;
        const float* Bs = As + 4096;
#pragma unroll
        for (int ks = 0; ks < 4; ks++) {
            const int kcol = (ks << 3) + lp;
            const int off0 = kcol ^ (q << 2);
            const int off4 = off0 ^ 4;
            uint32_t a[4][4];
#pragma unroll
            for (int mi = 0; mi < 4; mi++) {
                const float* ap = As + (((wm << 6) + (mi << 4) + q) << 5);
                a[mi][0] = __float_as_uint(ap[off0]);
                a[mi][1] = __float_as_uint(ap[256 + off0]);
                a[mi][2] = __float_as_uint(ap[off4]);
                a[mi][3] = __float_as_uint(ap[256 + off4]);
            }
#pragma unroll
            for (int nj = 0; nj < 4; nj++) {
                const float* bp = Bs + (kcol << 7)
                                     + (wn << 5) + ((nj ^ lp) << 3) + q;
                const uint32_t b0 = __float_as_uint(bp[0]);
                const uint32_t b1 = __float_as_uint(bp[512]);
#pragma unroll
                for (int mi = 0; mi < 4; mi++)
                    mma_tf32(acc[mi][nj], a[mi], b0, b1);
            }
        }
    }

#pragma unroll
    for (int mi = 0; mi < 4; mi++) {
        const int r0 = bm + (wm << 6) + (mi << 4) + q;
#pragma unroll
        for (int nj = 0; nj < 4; nj++) {
            const int col = bn + (wn << 5) + (nj << 3) + (lp << 1);
            const float bx = bias[col];
            const float by = bias[col + 1];
            if (MODE == 0) {
                const int which = col / DIMC;
                const int cc = col - which * DIMC;
                const int hh = cc >> 6;
                const int dd = cc & 63;
                const float sc = (which == 0) ? Q_SCALE : 1.0f;
                const int bb0 = r0 >> 11, nn0 = r0 & 2047;
                const int r1 = r0 + 8;
                const int bb1 = r1 >> 11, nn1 = r1 & 2047;
                const size_t base = (((size_t)which * BATCH) * NHEAD + hh) * SEQ * HDIM;
                float2 v0 = make_float2(f2tf32((acc[mi][nj][0] + bx) * sc),
                                        f2tf32((acc[mi][nj][1] + by) * sc));
                float2 v1 = make_float2(f2tf32((acc[mi][nj][2] + bx) * sc),
                                        f2tf32((acc[mi][nj][3] + by) * sc));
                *(float2*)&g_qkv[base + (((size_t)bb0 * NHEAD * SEQ) + nn0) * HDIM + dd] = v0;
                *(float2*)&g_qkv[base + (((size_t)bb1 * NHEAD * SEQ) + nn1) * HDIM + dd] = v1;
            } else {
                *(float2*)&Oout[(size_t)r0 * DIMC + col] =
                    make_float2(acc[mi][nj][0] + bx, acc[mi][nj][1] + by);
                *(float2*)&Oout[(size_t)(r0 + 8) * DIMC + col] =
                    make_float2(acc[mi][nj][2] + bx, acc[mi][nj][3] + by);
            }
        }
    }
}

// ---------------------------------------------------------------------------
// Flash attention (R14 structure, exp2 softmax): 64-key tiles, cp.async
// double-buffered, 104 KB smem -> 2 CTAs/SM. Scores arrive in exp2 domain
// (Q pre-scaled by 0.125*log2e), so softmax uses bare exp2f (no FMUL).
// ---------------------------------------------------------------------------
#define KSTR 68
#define VSTR 72
#define PSTR 68
#define OFFK0 0
#define OFFK1 (64 * KSTR)
#define OFFV0 (2 * 64 * KSTR)
#define OFFV1 (OFFV0 + 64 * VSTR)
#define OFFP  (OFFV0 + 2 * 64 * VSTR)
#define ATTN_SMEM_BYTES ((OFFP + 128 * PSTR) * 4)   // 106496

__global__ __launch_bounds__(256, 2)
void attn_mma_kernel()
{
    extern __shared__ float sm[];
    const uint32_t smb = smem_u32(sm);
    float* Ps = sm + OFFP;

    const int tid  = threadIdx.x;
    const int wid  = tid >> 5;
    const int lane = tid & 31;
    const int gq   = lane >> 2;
    const int gl   = lane & 3;
    const int q0   = blockIdx.x << 7;
    const int h    = blockIdx.y;
    const int b    = blockIdx.z;

    const size_t bh = ((size_t)b * NHEAD + h) * ((size_t)SEQ * HDIM);
    const float* Qg = g_qkv + bh + ((size_t)q0 << 6);
    const float* Kg = g_qkv + QKV_ONE + bh;
    const float* Vg = g_qkv + 2 * QKV_ONE + bh;

    // Stage Q (pre-rounded, pre-scaled) -> Ps, then register fragments
#pragma unroll
    for (int p = 0; p < 8; p++) {
        const int idx = tid + (p << 8);
        const int row = idx >> 4;
        const int c4  = (idx & 15) << 2;
        *(float4*)&Ps[row * PSTR + c4] = *(const float4*)(Qg + ((size_t)row << 6) + c4);
    }
    __syncthreads();

    const int qr = (wid << 4) + gq;
    uint32_t aq[8][4];
#pragma unroll
    for (int ks = 0; ks < 8; ks++) {
        const int kc = (ks << 3) + gl;
        aq[ks][0] = __float_as_uint(Ps[qr * PSTR + kc]);
        aq[ks][1] = __float_as_uint(Ps[(qr + 8) * PSTR + kc]);
        aq[ks][2] = __float_as_uint(Ps[qr * PSTR + kc + 4]);
        aq[ks][3] = __float_as_uint(Ps[(qr + 8) * PSTR + kc + 4]);
    }
    __syncthreads();   // Ps now free for P tiles

    // Prologue: stage K/V tile 0 -> buffer 0
    {
#pragma unroll
        for (int p = 0; p < 4; p++) {
            const int idx = tid + (p << 8);
            const int row = idx >> 4;
            const int c4  = (idx & 15) << 2;
            CP_ASYNC16(smb + (uint32_t)((OFFK0 + row * KSTR + c4) << 2),
                       Kg + ((size_t)row << 6) + c4);
            CP_ASYNC16(smb + (uint32_t)((OFFV0 + row * VSTR + c4) << 2),
                       Vg + ((size_t)row << 6) + c4);
        }
        CP_COMMIT();
    }

    float Oacc[8][4];
#pragma unroll
    for (int nj = 0; nj < 8; nj++)
#pragma unroll
        for (int r = 0; r < 4; r++) Oacc[nj][r] = 0.0f;
    float m0 = -1e30f, m1 = -1e30f, l0 = 0.0f, l1 = 0.0f;

    for (int kt = 0; kt < SEQ / 64; kt++) {
        CP_WAIT0();
        __syncthreads();

        if (kt + 1 < SEQ / 64) {
            const int koff = ((kt + 1) & 1) ? OFFK1 : OFFK0;
            const int voff = ((kt + 1) & 1) ? OFFV1 : OFFV0;
            const float* Kt = Kg + (((size_t)(kt + 1)) << 6) * HDIM;
            const float* Vt = Vg + (((size_t)(kt + 1)) << 6) * HDIM;
#pragma unroll
            for (int p = 0; p < 4; p++) {
                const int idx = tid + (p << 8);
                const int row = idx >> 4;
                const int c4  = (idx & 15) << 2;
                CP_ASYNC16(smb + (uint32_t)((koff + row * KSTR + c4) << 2),
                           Kt + ((size_t)row << 6) + c4);
                CP_ASYNC16(smb + (uint32_t)((voff + row * VSTR + c4) << 2),
                           Vt + ((size_t)row << 6) + c4);
            }
        }
        CP_COMMIT();

        const float* Ks = sm + ((kt & 1) ? OFFK1 : OFFK0);
        const float* Vs = sm + ((kt & 1) ? OFFV1 : OFFV0);

        // ---- S = Q K^T (scores in exp2 domain) ----
        float s[8][4];
#pragma unroll
        for (int nj = 0; nj < 8; nj++) {
            s[nj][0] = 0.0f; s[nj][1] = 0.0f; s[nj][2] = 0.0f; s[nj][3] = 0.0f;
            const int nrow = (nj << 3) + gq;
#pragma unroll
            for (int ks = 0; ks < 8; ks++) {
                const int kc = (ks << 3) + gl;
                mma_tf32(s[nj], aq[ks],
                         __float_as_uint(Ks[nrow * KSTR + kc]),
                         __float_as_uint(Ks[nrow * KSTR + kc + 4]));
            }
        }

        // ---- Online softmax in exp2 domain (quad reduce over lane bits 0,1) ----
        float c0 = -1e30f, c1 = -1e30f;
#pragma unroll
        for (int nj = 0; nj < 8; nj++) {
            c0 = fmaxf(c0, fmaxf(s[nj][0], s[nj][1]));
            c1 = fmaxf(c1, fmaxf(s[nj][2], s[nj][3]));
        }
        c0 = fmaxf(c0, __shfl_xor_sync(0xffffffffu, c0, 1));
        c0 = fmaxf(c0, __shfl_xor_sync(0xffffffffu, c0, 2));
        c1 = fmaxf(c1, __shfl_xor_sync(0xffffffffu, c1, 1));
        c1 = fmaxf(c1, __shfl_xor_sync(0xffffffffu, c1, 2));
        const float mn0 = fmaxf(m0, c0);
        const float mn1 = fmaxf(m1, c1);
        const float al0 = exp2f(m0 - mn0);
        const float al1 = exp2f(m1 - mn1);
        m0 = mn0; m1 = mn1;

        float r0 = 0.0f, r1 = 0.0f;
#pragma unroll
        for (int nj = 0; nj < 8; nj++) {
            s[nj][0] = exp2f(s[nj][0] - mn0);
            s[nj][1] = exp2f(s[nj][1] - mn0);
            s[nj][2] = exp2f(s[nj][2] - mn1);
            s[nj][3] = exp2f(s[nj][3] - mn1);
            r0 += s[nj][0] + s[nj][1];
            r1 += s[nj][2] + s[nj][3];
        }
        r0 += __shfl_xor_sync(0xffffffffu, r0, 1);
        r0 += __shfl_xor_sync(0xffffffffu, r0, 2);
        r1 += __shfl_xor_sync(0xffffffffu, r1, 1);
        r1 += __shfl_xor_sync(0xffffffffu, r1, 2);
        l0 = l0 * al0 + r0;
        l1 = l1 * al1 + r1;
#pragma unroll
        for (int nj = 0; nj < 8; nj++) {
            Oacc[nj][0] *= al0; Oacc[nj][1] *= al0;
            Oacc[nj][2] *= al1; Oacc[nj][3] *= al1;
        }

        // ---- P -> per-warp-private smem rows (qr, qr+8), tf32-rounded ----
#pragma unroll
        for (int nj = 0; nj < 8; nj++) {
            const int col = (nj << 3) + (gl << 1);
            *(float2*)&Ps[qr * PSTR + col] =
                make_float2(f2tf32(s[nj][0]), f2tf32(s[nj][1]));
            *(float2*)&Ps[(qr + 8) * PSTR + col] =
                make_float2(f2tf32(s[nj][2]), f2tf32(s[nj][3]));
        }
        __syncwarp();

        // ---- O += P V ----
#pragma unroll
        for (int ks = 0; ks < 8; ks++) {
            const int kc = (ks << 3) + gl;
            uint32_t pa[4];
            pa[0] = __float_as_uint(Ps[qr * PSTR + kc]);
            pa[1] = __float_as_uint(Ps[(qr + 8) * PSTR + kc]);
            pa[2] = __float_as_uint(Ps[qr * PSTR + kc + 4]);
            pa[3] = __float_as_uint(Ps[(qr + 8) * PSTR + kc + 4]);
#pragma unroll
            for (int nj = 0; nj < 8; nj++) {
                const int d = (nj << 3) + gq;
                mma_tf32(Oacc[nj], pa,
                         __float_as_uint(Vs[kc * VSTR + d]),
                         __float_as_uint(Vs[(kc + 4) * VSTR + d]));
            }
        }
    }

    // ---- Epilogue: normalize + tf32-round into g_attn ----
    const float inv0 = 1.0f / l0;
    const float inv1 = 1.0f / l1;
    const int n0 = q0 + qr;
    float* dst0 = &g_attn[((size_t)b * SEQ + n0) * DIMC + h * HDIM];
    float* dst1 = &g_attn[((size_t)b * SEQ + n0 + 8) * DIMC + h * HDIM];
#pragma unroll
    for (int nj = 0; nj < 8; nj++) {
        const int col = (nj << 3) + (gl << 1);
        *(float2*)(dst0 + col) = make_float2(f2tf32(Oacc[nj][0] * inv0),
                                             f2tf32(Oacc[nj][1] * inv0));
        *(float2*)(dst1 + col) = make_float2(f2tf32(Oacc[nj][2] * inv1),
                                             f2tf32(Oacc[nj][3] * inv1));
    }
}

// ---------------------------------------------------------------------------
extern "C" void kernel_launch(void* const* d_in, const int* in_sizes, int n_in,
                              void* d_out, int out_size)
{
    (void)in_sizes; (void)n_in; (void)out_size;
    const float* x      = (const float*)d_in[0];
    const float* w_qkv  = (const float*)d_in[1];
    const float* b_qkv  = (const float*)d_in[2];
    const float* w_proj = (const float*)d_in[3];
    const float* b_proj = (const float*)d_in[4];
    float* out = (float*)d_out;

    cudaFuncSetAttribute(mma_gemm<0>, cudaFuncAttributeMaxDynamicSharedMemorySize, GEMM_SMEM_BYTES);
    cudaFuncSetAttribute(mma_gemm<1>, cudaFuncAttributeMaxDynamicSharedMemorySize, GEMM_SMEM_BYTES);
    cudaFuncSetAttribute(attn_mma_kernel, cudaFuncAttributeMaxDynamicSharedMemorySize, ATTN_SMEM_BYTES);

    // 0) Pre-round inputs to tf32 (single merged launch)
    round_tf32_all<<<2048, 256>>>((const float4*)x, (const float4*)w_qkv,
                                  (const float4*)w_proj);

    // 1) QKV GEMM -> g_qkv (rounded, Q pre-scaled by 0.125*log2e)
    {
        dim3 grid(MROWS / 128, 3 * DIMC / 128);
        mma_gemm<0><<<grid, 256, GEMM_SMEM_BYTES>>>(b_qkv, nullptr);
    }
    // 2) Attention -> g_attn (rounded); 2 CTAs/SM
    {
        dim3 grid(SEQ / 128, NHEAD, BATCH);
        attn_mma_kernel<<<grid, 256, ATTN_SMEM_BYTES>>>();
    }
    // 3) Projection -> d_out (fp32)
    {
        dim3 grid(MROWS / 128, DIMC / 128);
        mma_gemm<1><<<grid, 256, GEMM_SMEM_BYTES>>>(b_proj, out);
    }
}